// round 4
// baseline (speedup 1.0000x reference)
#include <cuda_runtime.h>
#include <cstdint>

// Problem constants (fixed shapes)
#define BL_   2048           // B*L = 2*1024
#define L_    1024
#define D_    1024
#define ED_   2048
#define N_    16
#define R_    32
#define NPROJ 4096           // 2*ED
#define SPLITK 16

// ---------------- device scratch (static, no allocation) ----------------
__device__ float g_xs  [BL_ * ED_];
__device__ float g_z   [BL_ * ED_];
__device__ float g_xsc [BL_ * ED_];
__device__ float g_xdbl[BL_ * 64];
__device__ float g_xdbl_part[SPLITK][BL_ * 64];
__device__ float g_delta[BL_ * ED_];
__device__ float g_y   [BL_ * ED_];
__device__ float g_A   [ED_ * N_];

// ---------------- helpers ----------------
__device__ __forceinline__ uint32_t smem_u32(const void* p) {
    uint32_t a;
    asm("{ .reg .u64 t; cvta.to.shared.u64 t, %1; cvt.u32.u64 %0, t; }" : "=r"(a) : "l"(p));
    return a;
}
__device__ __forceinline__ uint32_t tf32_hi_bits(float a) {
    uint32_t b;
    asm("cvt.rna.tf32.f32 %0, %1;" : "=r"(b) : "f"(a));
    return b;
}

#define CP16(dst, src) \
    asm volatile("cp.async.cg.shared.global [%0], [%1], 16;" :: "r"(dst), "l"(src))
#define CP_COMMIT() asm volatile("cp.async.commit_group;")
template<int N> __device__ __forceinline__ void cp_wait() {
    asm volatile("cp.async.wait_group %0;" :: "n"(N));
}

#define MMA_TF32(c, a0, a1, a2, a3, b0, b1) \
    asm volatile("mma.sync.aligned.m16n8k8.row.col.f32.tf32.tf32.f32 " \
        "{%0,%1,%2,%3}, {%4,%5,%6,%7}, {%8,%9}, {%0,%1,%2,%3};" \
        : "+f"((c)[0]), "+f"((c)[1]), "+f"((c)[2]), "+f"((c)[3]) \
        : "r"(a0), "r"(a1), "r"(a2), "r"(a3), "r"(b0), "r"(b1))

// ============================================================
// 3xTF32 mma.sync GEMM: C[m][n] = sum_k A[m][k] * B[n][k]
// CTA 128x128, BK=32, 8 warps (2m x 4n), warp tile 64x32.
// SMEM: fp32 tiles, rows padded to 36 floats. cp.async double buffer.
// 2 CTAs per SM co-resident (147 KB SMEM total).
// EPI 0: C[m*Nout + n]
// EPI 1: n0<2048 -> g_xs ; else -> g_z (col n-2048)
// ============================================================
#define SROW 36                      // padded row, floats
#define ATILE_F (128 * SROW)         // 4608 floats
#define STAGE_F (2 * ATILE_F)        // A + B per stage = 9216 floats
#define STAGE_B (STAGE_F * 4)        // 36864 bytes

template<int EPI>
__global__ void __launch_bounds__(256, 2)
gemm_mma(const float* __restrict__ A, const float* __restrict__ B,
         float* __restrict__ C, int Nout, int K)
{
    extern __shared__ float sm[];
    const int tid  = threadIdx.x;
    const int wid  = tid >> 5;
    const int lane = tid & 31;
    const int gq   = lane >> 2;          // groupID 0..7
    const int tig  = lane & 3;           // thread-in-group 0..3
    const int m0   = blockIdx.y * 128;
    const int n0   = blockIdx.x * 128;
    const int wm   = (wid >> 2) * 64;    // warp m offset
    const int wn   = (wid & 3) * 32;     // warp n offset
    const int NC   = K >> 5;

    float acc[4][4][4];
#pragma unroll
    for (int i = 0; i < 4; i++)
#pragma unroll
        for (int j = 0; j < 4; j++)
#pragma unroll
            for (int q = 0; q < 4; q++) acc[i][j][q] = 0.f;

    const uint32_t sbase = smem_u32(sm);
    const int lr  = tid >> 3;            // 0..31 loader row
    const int lc4 = (tid & 7) << 2;      // loader col (floats)
    const float* ga = A + (size_t)(m0 + lr) * K + lc4;
    const float* gb = B + (size_t)(n0 + lr) * K + lc4;
    const uint32_t sa_off = (uint32_t)(lr * SROW + lc4) * 4;

    // ---- prologue: issue chunks 0 and 1 ----
#pragma unroll
    for (int c = 0; c < 2; c++) {
        uint32_t sa = sbase + c * STAGE_B + sa_off;
        uint32_t sbb = sa + ATILE_F * 4;
        const float* pa = ga + c * 32;
        const float* pb = gb + c * 32;
#pragma unroll
        for (int i = 0; i < 4; i++) {
            CP16(sa  + i * 32 * SROW * 4, pa + (size_t)(i * 32) * K);
            CP16(sbb + i * 32 * SROW * 4, pb + (size_t)(i * 32) * K);
        }
        CP_COMMIT();
    }
    cp_wait<1>();
    __syncthreads();

    for (int c = 0; c < NC; c++) {
        const int buf = c & 1;
        const float* As = sm + buf * STAGE_F;
        const float* Bs = As + ATILE_F;

#pragma unroll
        for (int ks = 0; ks < 4; ks++) {
            // B fragments for 4 n-tiles (hi/lo)
            uint32_t bhi[4][2], blo[4][2];
#pragma unroll
            for (int nt = 0; nt < 4; nt++) {
                const float* bp = Bs + (wn + 8 * nt + gq) * SROW + ks * 8 + tig;
                float b0 = bp[0], b1 = bp[4];
                bhi[nt][0] = tf32_hi_bits(b0);
                bhi[nt][1] = tf32_hi_bits(b1);
                blo[nt][0] = __float_as_uint(b0 - __uint_as_float(bhi[nt][0]));
                blo[nt][1] = __float_as_uint(b1 - __uint_as_float(bhi[nt][1]));
            }
#pragma unroll
            for (int mt = 0; mt < 4; mt++) {
                const float* ap = As + (wm + 16 * mt + gq) * SROW + ks * 8 + tig;
                float a0 = ap[0], a1 = ap[8 * SROW], a2 = ap[4], a3 = ap[8 * SROW + 4];
                uint32_t ah0 = tf32_hi_bits(a0), ah1 = tf32_hi_bits(a1);
                uint32_t ah2 = tf32_hi_bits(a2), ah3 = tf32_hi_bits(a3);
                uint32_t al0 = __float_as_uint(a0 - __uint_as_float(ah0));
                uint32_t al1 = __float_as_uint(a1 - __uint_as_float(ah1));
                uint32_t al2 = __float_as_uint(a2 - __uint_as_float(ah2));
                uint32_t al3 = __float_as_uint(a3 - __uint_as_float(ah3));
#pragma unroll
                for (int nt = 0; nt < 4; nt++) {
                    MMA_TF32(acc[mt][nt], ah0, ah1, ah2, ah3, bhi[nt][0], bhi[nt][1]);
                    MMA_TF32(acc[mt][nt], ah0, ah1, ah2, ah3, blo[nt][0], blo[nt][1]);
                    MMA_TF32(acc[mt][nt], al0, al1, al2, al3, bhi[nt][0], bhi[nt][1]);
                }
            }
        }
        __syncthreads();   // all warps done reading buf

        if (c + 2 < NC) {
            uint32_t sa = sbase + buf * STAGE_B + sa_off;
            uint32_t sbb = sa + ATILE_F * 4;
            const float* pa = ga + (c + 2) * 32;
            const float* pb = gb + (c + 2) * 32;
#pragma unroll
            for (int i = 0; i < 4; i++) {
                CP16(sa  + i * 32 * SROW * 4, pa + (size_t)(i * 32) * K);
                CP16(sbb + i * 32 * SROW * 4, pb + (size_t)(i * 32) * K);
            }
            CP_COMMIT();
            cp_wait<1>();
        } else {
            cp_wait<0>();
        }
        __syncthreads();
    }

    // ---- epilogue ----
    float* dst;
    int ld, ncol0;
    if (EPI == 1) {
        if (n0 < ED_) { dst = g_xs; ncol0 = n0; }
        else          { dst = g_z;  ncol0 = n0 - ED_; }
        ld = ED_;
    } else {
        dst = C; ncol0 = n0; ld = Nout;
    }
#pragma unroll
    for (int mt = 0; mt < 4; mt++) {
        const int m = m0 + wm + 16 * mt + gq;
#pragma unroll
        for (int nt = 0; nt < 4; nt++) {
            const int n = ncol0 + wn + 8 * nt + 2 * tig;
            float2 v0 = make_float2(acc[mt][nt][0], acc[mt][nt][1]);
            float2 v1 = make_float2(acc[mt][nt][2], acc[mt][nt][3]);
            *(float2*)(dst + (size_t)m * ld + n)       = v0;
            *(float2*)(dst + (size_t)(m + 8) * ld + n) = v1;
        }
    }
}

// ---------------- tiny precompute: A = -exp(A_log) ----------------
__global__ void prep_A_kernel(const float* __restrict__ A_log) {
    int i = blockIdx.x * blockDim.x + threadIdx.x;
    if (i < ED_ * N_) g_A[i] = -expf(A_log[i]);
}

// ---------------- split-K SIMT GEMM for x_proj ----------------
// grid (1, M/64, SPLITK); block 256. K-slice = K/SPLITK = 128.
__global__ void __launch_bounds__(256)
gemm_xproj_sk(const float* __restrict__ A, const float* __restrict__ B, int K)
{
    constexpr int BM = 64, BN = 64, BK = 16, TM = 4, TN = 4;
    __shared__ float As[BK * BM];
    __shared__ float Bs[BK * BN];

    const int t  = threadIdx.x;
    const int m0 = blockIdx.y * BM;
    const int z  = blockIdx.z;
    const int KS = K / SPLITK;
    const int kbeg = z * KS;
    const int tr = t / (BN / TN);
    const int tc = t % (BN / TN);

    float acc[TM][TN];
#pragma unroll
    for (int i = 0; i < TM; i++)
#pragma unroll
        for (int j = 0; j < TN; j++) acc[i][j] = 0.f;

    for (int k0 = kbeg; k0 < kbeg + KS; k0 += BK) {
        {
            int row = t / (BK / 4);
            int cc  = t % (BK / 4);
            float4 v = *(const float4*)(A + (size_t)(m0 + row) * K + k0 + cc * 4);
            As[(cc * 4 + 0) * BM + row] = v.x;
            As[(cc * 4 + 1) * BM + row] = v.y;
            As[(cc * 4 + 2) * BM + row] = v.z;
            As[(cc * 4 + 3) * BM + row] = v.w;
            float4 w = *(const float4*)(B + (size_t)row * K + k0 + cc * 4);
            Bs[(cc * 4 + 0) * BN + row] = w.x;
            Bs[(cc * 4 + 1) * BN + row] = w.y;
            Bs[(cc * 4 + 2) * BN + row] = w.z;
            Bs[(cc * 4 + 3) * BN + row] = w.w;
        }
        __syncthreads();
#pragma unroll
        for (int kk = 0; kk < BK; kk++) {
            float af[TM], bf[TN];
#pragma unroll
            for (int i = 0; i < TM; i++) af[i] = As[kk * BM + tr * TM + i];
#pragma unroll
            for (int j = 0; j < TN; j++) bf[j] = Bs[kk * BN + tc * TN + j];
#pragma unroll
            for (int i = 0; i < TM; i++)
#pragma unroll
                for (int j = 0; j < TN; j++)
                    acc[i][j] = fmaf(af[i], bf[j], acc[i][j]);
        }
        __syncthreads();
    }
#pragma unroll
    for (int i = 0; i < TM; i++) {
        int m = m0 + tr * TM + i;
#pragma unroll
        for (int j = 0; j < TN; j++) {
            int n = tc * TN + j;
            g_xdbl_part[z][(size_t)m * 64 + n] = acc[i][j];
        }
    }
}

__global__ void reduce_xdbl_kernel() {
    int i = blockIdx.x * blockDim.x + threadIdx.x;
    if (i >= BL_ * 64 / 4) return;
    float4 s = make_float4(0.f, 0.f, 0.f, 0.f);
#pragma unroll
    for (int z = 0; z < SPLITK; z++) {
        float4 v = *((const float4*)g_xdbl_part[z] + i);
        s.x += v.x; s.y += v.y; s.z += v.z; s.w += v.w;
    }
    *((float4*)g_xdbl + i) = s;
}

// ---------------- depthwise conv1d (k=3, pad 1) + silu ----------------
__global__ void conv_silu_kernel(const float* __restrict__ w,
                                 const float* __restrict__ b)
{
    int idx = blockIdx.x * blockDim.x + threadIdx.x;
    if (idx >= BL_ * (ED_ / 4)) return;
    int m  = idx >> 9;
    int e4 = idx & 511;
    int e  = e4 * 4;
    int l  = m & (L_ - 1);

    float4 cur  = *(const float4*)(g_xs + (size_t)m * ED_ + e);
    float4 prev = (l > 0)    ? *(const float4*)(g_xs + (size_t)(m - 1) * ED_ + e)
                             : make_float4(0.f, 0.f, 0.f, 0.f);
    float4 nxt  = (l < L_-1) ? *(const float4*)(g_xs + (size_t)(m + 1) * ED_ + e)
                             : make_float4(0.f, 0.f, 0.f, 0.f);

    float4 w0 = *(const float4*)(w + (size_t)e * 3);
    float4 w1 = *(const float4*)(w + (size_t)e * 3 + 4);
    float4 w2 = *(const float4*)(w + (size_t)e * 3 + 8);
    float4 bb = *(const float4*)(b + e);

    float r0 = fmaf(prev.x, w0.x, fmaf(cur.x, w0.y, fmaf(nxt.x, w0.z, bb.x)));
    float r1 = fmaf(prev.y, w0.w, fmaf(cur.y, w1.x, fmaf(nxt.y, w1.y, bb.y)));
    float r2 = fmaf(prev.z, w1.z, fmaf(cur.z, w1.w, fmaf(nxt.z, w2.x, bb.z)));
    float r3 = fmaf(prev.w, w2.y, fmaf(cur.w, w2.z, fmaf(nxt.w, w2.w, bb.w)));

    float4 o;
    o.x = r0 * (1.f / (1.f + __expf(-r0)));
    o.y = r1 * (1.f / (1.f + __expf(-r1)));
    o.z = r2 * (1.f / (1.f + __expf(-r2)));
    o.w = r3 * (1.f / (1.f + __expf(-r3)));
    *(float4*)(g_xsc + (size_t)m * ED_ + e) = o;
}

// ---------------- delta = softplus(x_dbl[:, :32] @ dt_proj_w^T + b) ----------------
__global__ void delta_kernel(const float* __restrict__ W,
                             const float* __restrict__ bias)
{
    int mg = blockIdx.x >> 3;
    int e  = ((blockIdx.x & 7) << 8) + threadIdx.x;

    __shared__ float sx[8][32];
    {
        int i  = threadIdx.x;
        int mm = i >> 5, r = i & 31;
        sx[mm][r] = g_xdbl[(size_t)(mg * 8 + mm) * 64 + r];
    }
    __syncthreads();

    float wr[32];
#pragma unroll
    for (int q = 0; q < 8; q++) {
        float4 v = *(const float4*)(W + (size_t)e * 32 + q * 4);
        wr[q * 4 + 0] = v.x; wr[q * 4 + 1] = v.y; wr[q * 4 + 2] = v.z; wr[q * 4 + 3] = v.w;
    }
    float bv = bias[e];

#pragma unroll
    for (int mm = 0; mm < 8; mm++) {
        float acc = bv;
#pragma unroll
        for (int r = 0; r < 32; r++) acc = fmaf(sx[mm][r], wr[r], acc);
        float sp = (acc > 20.f) ? acc : log1pf(__expf(acc));
        g_delta[(size_t)(mg * 8 + mm) * ED_ + e] = sp;
    }
}

// ---------------- fused SSM step ----------------
__global__ void ssm_kernel(const float* __restrict__ h,
                           const float* __restrict__ Dvec,
                           float* __restrict__ hout)
{
    int tid = threadIdx.x;
    int m   = blockIdx.x >> 3;
    int e   = ((blockIdx.x & 7) << 8) + tid;

    __shared__ float sB[N_], sC[N_];
    if (tid < N_)          sB[tid]      = g_xdbl[(size_t)m * 64 + 32 + tid];
    else if (tid < 2*N_)   sC[tid - N_] = g_xdbl[(size_t)m * 64 + 32 + tid];
    __syncthreads();

    size_t me = (size_t)m * ED_ + e;
    float delta = g_delta[me];
    float xs    = g_xsc[me];
    float z     = g_z[me];
    float dx    = delta * xs;

    const float4* h4 = (const float4*)(h + me * N_);
    float4*       o4 = (float4*)(hout + me * N_);
    const float4* a4 = (const float4*)(g_A + (size_t)e * N_);

    float y = 0.f;
#pragma unroll
    for (int q = 0; q < 4; q++) {
        float4 hv = h4[q];
        float4 av = a4[q];
        float4 o;
        o.x = fmaf(__expf(delta * av.x), hv.x, dx * sB[q*4+0]);
        o.y = fmaf(__expf(delta * av.y), hv.y, dx * sB[q*4+1]);
        o.z = fmaf(__expf(delta * av.z), hv.z, dx * sB[q*4+2]);
        o.w = fmaf(__expf(delta * av.w), hv.w, dx * sB[q*4+3]);
        o4[q] = o;
        y = fmaf(o.x, sC[q*4+0], y);
        y = fmaf(o.y, sC[q*4+1], y);
        y = fmaf(o.z, sC[q*4+2], y);
        y = fmaf(o.w, sC[q*4+3], y);
    }
    y = fmaf(Dvec[e], xs, y);
    float sz = z * (1.f / (1.f + __expf(-z)));
    g_y[me] = y * sz;
}

// ---------------- launch ----------------
extern "C" void kernel_launch(void* const* d_in, const int* in_sizes, int n_in,
                              void* d_out, int out_size)
{
    const float* x          = (const float*)d_in[0];
    const float* h          = (const float*)d_in[1];
    const float* in_proj_w  = (const float*)d_in[2];
    const float* conv_w     = (const float*)d_in[3];
    const float* conv_b     = (const float*)d_in[4];
    const float* x_proj_w   = (const float*)d_in[5];
    const float* dt_proj_w  = (const float*)d_in[6];
    const float* dt_proj_b  = (const float*)d_in[7];
    const float* A_log      = (const float*)d_in[8];
    const float* Dvec       = (const float*)d_in[9];
    const float* out_proj_w = (const float*)d_in[10];

    float* out  = (float*)d_out;
    float* hout = out + (size_t)BL_ * D_;

    float* p_xsc = nullptr;
    float* p_y   = nullptr;
    cudaGetSymbolAddress((void**)&p_xsc, g_xsc);
    cudaGetSymbolAddress((void**)&p_y,   g_y);

    const int SMEM_GEMM = 2 * STAGE_B;   // 73728 bytes
    cudaFuncSetAttribute(gemm_mma<0>, cudaFuncAttributeMaxDynamicSharedMemorySize, SMEM_GEMM);
    cudaFuncSetAttribute(gemm_mma<1>, cudaFuncAttributeMaxDynamicSharedMemorySize, SMEM_GEMM);

    // 1. A = -exp(A_log)
    prep_A_kernel<<<(ED_ * N_ + 255) / 256, 256>>>(A_log);

    // 2. in_proj GEMM (3xTF32 mma.sync): (2048x1024) x (4096x1024)^T -> split xs / z
    gemm_mma<1><<<dim3(NPROJ / 128, BL_ / 128), 256, SMEM_GEMM>>>(
        x, in_proj_w, nullptr, NPROJ, D_);

    // 3. depthwise conv + silu
    conv_silu_kernel<<<(BL_ * (ED_ / 4) + 255) / 256, 256>>>(conv_w, conv_b);

    // 4. x_proj GEMM (split-K SIMT) + reduce
    gemm_xproj_sk<<<dim3(1, BL_ / 64, SPLITK), 256>>>(p_xsc, x_proj_w, ED_);
    reduce_xdbl_kernel<<<(BL_ * 64 / 4 + 255) / 256, 256>>>();

    // 5. dt_proj + softplus -> delta
    delta_kernel<<<(BL_ / 8) * 8, 256>>>(dt_proj_w, dt_proj_b);

    // 6. fused SSM (writes h_new to output + y*silu(z) scratch)
    ssm_kernel<<<BL_ * 8, 256>>>(h, Dvec, hout);

    // 7. out_proj GEMM (3xTF32 mma.sync): (2048x2048) x (1024x2048)^T -> out
    gemm_mma<0><<<dim3(D_ / 128, BL_ / 128), 256, SMEM_GEMM>>>(
        p_y, out_proj_w, out, D_, ED_);
}

// round 5
// speedup vs baseline: 1.0508x; 1.0508x over previous
#include <cuda_runtime.h>
#include <cstdint>

// Problem constants (fixed shapes)
#define BL_   2048           // B*L = 2*1024
#define L_    1024
#define D_    1024
#define ED_   2048
#define N_    16
#define R_    32
#define NPROJ 4096           // 2*ED
#define SPLITK 16

// ---------------- device scratch (static, no allocation) ----------------
__device__ float g_xs  [BL_ * ED_];
__device__ float g_z   [BL_ * ED_];
__device__ float g_xsc [BL_ * ED_];
__device__ float g_xdbl[BL_ * 64];
__device__ float g_xdbl_part[SPLITK][BL_ * 64];
__device__ float g_delta[BL_ * ED_];
__device__ float g_y   [BL_ * ED_];
__device__ float g_A   [ED_ * N_];

// ---------------- helpers ----------------
__device__ __forceinline__ uint32_t smem_u32(const void* p) {
    uint32_t a;
    asm("{ .reg .u64 t; cvta.to.shared.u64 t, %1; cvt.u32.u64 %0, t; }" : "=r"(a) : "l"(p));
    return a;
}
__device__ __forceinline__ uint32_t tf32_hi_bits(float a) {
    uint32_t b;
    asm("cvt.rna.tf32.f32 %0, %1;" : "=r"(b) : "f"(a));
    return b;
}

#define CP16(dst, src) \
    asm volatile("cp.async.cg.shared.global [%0], [%1], 16;" :: "r"(dst), "l"(src))
#define CP_COMMIT() asm volatile("cp.async.commit_group;")
template<int N> __device__ __forceinline__ void cp_wait() {
    asm volatile("cp.async.wait_group %0;" :: "n"(N));
}

#define MMA_TF32(c, a0, a1, a2, a3, b0, b1) \
    asm volatile("mma.sync.aligned.m16n8k8.row.col.f32.tf32.tf32.f32 " \
        "{%0,%1,%2,%3}, {%4,%5,%6,%7}, {%8,%9}, {%0,%1,%2,%3};" \
        : "+f"((c)[0]), "+f"((c)[1]), "+f"((c)[2]), "+f"((c)[3]) \
        : "r"(a0), "r"(a1), "r"(a2), "r"(a3), "r"(b0), "r"(b1))

// ============================================================
// 3xTF32 mma.sync GEMM: C[m][n] = sum_k A[m][k] * B[n][k]
// CTA tile 64x128, BK=32. 128 threads = 4 warps (2m x 2n),
// warp tile 32x64 -> fat warps minimize SMEM frag traffic.
// fp32 single-copy SMEM (rows padded to 36 floats), cp.async
// double buffer, hi/lo tf32 split in registers.
// EPI 0: C[m*Nout + n]
// EPI 1: n0<2048 -> g_xs ; else -> g_z (col n-2048)
// ============================================================
#define SROW 36                       // padded row, floats
#define ATF_A (64 * SROW)             // A tile floats (2304)
#define ATF_B (128 * SROW)            // B tile floats (4608)
#define STAGE_F (ATF_A + ATF_B)       // 6912 floats
#define STAGE_B (STAGE_F * 4)         // 27648 bytes

template<int EPI>
__global__ void __launch_bounds__(128, 2)
gemm_mma(const float* __restrict__ A, const float* __restrict__ B,
         float* __restrict__ C, int Nout, int K)
{
    extern __shared__ float sm[];
    const int tid  = threadIdx.x;
    const int wid  = tid >> 5;           // 0..3
    const int lane = tid & 31;
    const int gq   = lane >> 2;          // 0..7
    const int tig  = lane & 3;           // 0..3
    const int m0   = blockIdx.y * 64;
    const int n0   = blockIdx.x * 128;
    const int wm   = (wid >> 1) * 32;    // warp m offset (0/32)
    const int wn   = (wid & 1) * 64;     // warp n offset (0/64)
    const int NC   = K >> 5;

    float acc[2][8][4];
#pragma unroll
    for (int i = 0; i < 2; i++)
#pragma unroll
        for (int j = 0; j < 8; j++)
#pragma unroll
            for (int q = 0; q < 4; q++) acc[i][j][q] = 0.f;

    const uint32_t sbase = smem_u32(sm);
    const int lr  = tid >> 3;            // 0..15 loader row
    const int lc4 = (tid & 7) << 2;      // loader col (floats)
    const float* ga = A + (size_t)(m0 + lr) * K + lc4;
    const float* gb = B + (size_t)(n0 + lr) * K + lc4;
    const uint32_t s_off = (uint32_t)(lr * SROW + lc4) * 4;

    // ---- prologue: issue chunks 0 and 1 ----
#pragma unroll
    for (int c = 0; c < 2; c++) {
        uint32_t sa  = sbase + c * STAGE_B + s_off;
        uint32_t sbb = sa + ATF_A * 4;
        const float* pa = ga + c * 32;
        const float* pb = gb + c * 32;
#pragma unroll
        for (int i = 0; i < 4; i++)      // A: 64 rows
            CP16(sa + i * 16 * SROW * 4, pa + (size_t)(i * 16) * K);
#pragma unroll
        for (int i = 0; i < 8; i++)      // B: 128 rows
            CP16(sbb + i * 16 * SROW * 4, pb + (size_t)(i * 16) * K);
        CP_COMMIT();
    }
    cp_wait<1>();
    __syncthreads();

    for (int c = 0; c < NC; c++) {
        const int buf = c & 1;
        const float* As = sm + buf * STAGE_F;
        const float* Bs = As + ATF_A;

#pragma unroll
        for (int ks = 0; ks < 4; ks++) {
            // B fragments for 8 n-tiles (hi/lo)
            uint32_t bhi[8][2], blo[8][2];
#pragma unroll
            for (int nt = 0; nt < 8; nt++) {
                const float* bp = Bs + (wn + 8 * nt + gq) * SROW + ks * 8 + tig;
                float b0 = bp[0], b1 = bp[4];
                bhi[nt][0] = tf32_hi_bits(b0);
                bhi[nt][1] = tf32_hi_bits(b1);
                blo[nt][0] = __float_as_uint(b0 - __uint_as_float(bhi[nt][0]));
                blo[nt][1] = __float_as_uint(b1 - __uint_as_float(bhi[nt][1]));
            }
#pragma unroll
            for (int mt = 0; mt < 2; mt++) {
                const float* ap = As + (wm + 16 * mt + gq) * SROW + ks * 8 + tig;
                float a0 = ap[0], a1 = ap[8 * SROW], a2 = ap[4], a3 = ap[8 * SROW + 4];
                uint32_t ah0 = tf32_hi_bits(a0), ah1 = tf32_hi_bits(a1);
                uint32_t ah2 = tf32_hi_bits(a2), ah3 = tf32_hi_bits(a3);
                uint32_t al0 = __float_as_uint(a0 - __uint_as_float(ah0));
                uint32_t al1 = __float_as_uint(a1 - __uint_as_float(ah1));
                uint32_t al2 = __float_as_uint(a2 - __uint_as_float(ah2));
                uint32_t al3 = __float_as_uint(a3 - __uint_as_float(ah3));
#pragma unroll
                for (int nt = 0; nt < 8; nt++) {
                    MMA_TF32(acc[mt][nt], ah0, ah1, ah2, ah3, bhi[nt][0], bhi[nt][1]);
                    MMA_TF32(acc[mt][nt], ah0, ah1, ah2, ah3, blo[nt][0], blo[nt][1]);
                    MMA_TF32(acc[mt][nt], al0, al1, al2, al3, bhi[nt][0], bhi[nt][1]);
                }
            }
        }
        __syncthreads();   // all warps done reading buf

        if (c + 2 < NC) {
            uint32_t sa  = sbase + buf * STAGE_B + s_off;
            uint32_t sbb = sa + ATF_A * 4;
            const float* pa = ga + (c + 2) * 32;
            const float* pb = gb + (c + 2) * 32;
#pragma unroll
            for (int i = 0; i < 4; i++)
                CP16(sa + i * 16 * SROW * 4, pa + (size_t)(i * 16) * K);
#pragma unroll
            for (int i = 0; i < 8; i++)
                CP16(sbb + i * 16 * SROW * 4, pb + (size_t)(i * 16) * K);
            CP_COMMIT();
            cp_wait<1>();
        } else {
            cp_wait<0>();
        }
        __syncthreads();
    }

    // ---- epilogue ----
    float* dst;
    int ld, ncol0;
    if (EPI == 1) {
        if (n0 < ED_) { dst = g_xs; ncol0 = n0; }
        else          { dst = g_z;  ncol0 = n0 - ED_; }
        ld = ED_;
    } else {
        dst = C; ncol0 = n0; ld = Nout;
    }
#pragma unroll
    for (int mt = 0; mt < 2; mt++) {
        const int m = m0 + wm + 16 * mt + gq;
#pragma unroll
        for (int nt = 0; nt < 8; nt++) {
            const int n = ncol0 + wn + 8 * nt + 2 * tig;
            float2 v0 = make_float2(acc[mt][nt][0], acc[mt][nt][1]);
            float2 v1 = make_float2(acc[mt][nt][2], acc[mt][nt][3]);
            *(float2*)(dst + (size_t)m * ld + n)       = v0;
            *(float2*)(dst + (size_t)(m + 8) * ld + n) = v1;
        }
    }
}

// ---------------- tiny precompute: A = -exp(A_log) ----------------
__global__ void prep_A_kernel(const float* __restrict__ A_log) {
    int i = blockIdx.x * blockDim.x + threadIdx.x;
    if (i < ED_ * N_) g_A[i] = -expf(A_log[i]);
}

// ---------------- split-K SIMT GEMM for x_proj ----------------
// grid (1, M/64, SPLITK); block 256. K-slice = K/SPLITK = 128.
__global__ void __launch_bounds__(256)
gemm_xproj_sk(const float* __restrict__ A, const float* __restrict__ B, int K)
{
    constexpr int BM = 64, BN = 64, BK = 16, TM = 4, TN = 4;
    __shared__ float As[BK * BM];
    __shared__ float Bs[BK * BN];

    const int t  = threadIdx.x;
    const int m0 = blockIdx.y * BM;
    const int z  = blockIdx.z;
    const int KS = K / SPLITK;
    const int kbeg = z * KS;
    const int tr = t / (BN / TN);
    const int tc = t % (BN / TN);

    float acc[TM][TN];
#pragma unroll
    for (int i = 0; i < TM; i++)
#pragma unroll
        for (int j = 0; j < TN; j++) acc[i][j] = 0.f;

    for (int k0 = kbeg; k0 < kbeg + KS; k0 += BK) {
        {
            int row = t / (BK / 4);
            int cc  = t % (BK / 4);
            float4 v = *(const float4*)(A + (size_t)(m0 + row) * K + k0 + cc * 4);
            As[(cc * 4 + 0) * BM + row] = v.x;
            As[(cc * 4 + 1) * BM + row] = v.y;
            As[(cc * 4 + 2) * BM + row] = v.z;
            As[(cc * 4 + 3) * BM + row] = v.w;
            float4 w = *(const float4*)(B + (size_t)row * K + k0 + cc * 4);
            Bs[(cc * 4 + 0) * BN + row] = w.x;
            Bs[(cc * 4 + 1) * BN + row] = w.y;
            Bs[(cc * 4 + 2) * BN + row] = w.z;
            Bs[(cc * 4 + 3) * BN + row] = w.w;
        }
        __syncthreads();
#pragma unroll
        for (int kk = 0; kk < BK; kk++) {
            float af[TM], bf[TN];
#pragma unroll
            for (int i = 0; i < TM; i++) af[i] = As[kk * BM + tr * TM + i];
#pragma unroll
            for (int j = 0; j < TN; j++) bf[j] = Bs[kk * BN + tc * TN + j];
#pragma unroll
            for (int i = 0; i < TM; i++)
#pragma unroll
                for (int j = 0; j < TN; j++)
                    acc[i][j] = fmaf(af[i], bf[j], acc[i][j]);
        }
        __syncthreads();
    }
#pragma unroll
    for (int i = 0; i < TM; i++) {
        int m = m0 + tr * TM + i;
#pragma unroll
        for (int j = 0; j < TN; j++) {
            int n = tc * TN + j;
            g_xdbl_part[z][(size_t)m * 64 + n] = acc[i][j];
        }
    }
}

__global__ void reduce_xdbl_kernel() {
    int i = blockIdx.x * blockDim.x + threadIdx.x;
    if (i >= BL_ * 64 / 4) return;
    float4 s = make_float4(0.f, 0.f, 0.f, 0.f);
#pragma unroll
    for (int z = 0; z < SPLITK; z++) {
        float4 v = *((const float4*)g_xdbl_part[z] + i);
        s.x += v.x; s.y += v.y; s.z += v.z; s.w += v.w;
    }
    *((float4*)g_xdbl + i) = s;
}

// ---------------- depthwise conv1d (k=3, pad 1) + silu ----------------
__global__ void conv_silu_kernel(const float* __restrict__ w,
                                 const float* __restrict__ b)
{
    int idx = blockIdx.x * blockDim.x + threadIdx.x;
    if (idx >= BL_ * (ED_ / 4)) return;
    int m  = idx >> 9;
    int e4 = idx & 511;
    int e  = e4 * 4;
    int l  = m & (L_ - 1);

    float4 cur  = *(const float4*)(g_xs + (size_t)m * ED_ + e);
    float4 prev = (l > 0)    ? *(const float4*)(g_xs + (size_t)(m - 1) * ED_ + e)
                             : make_float4(0.f, 0.f, 0.f, 0.f);
    float4 nxt  = (l < L_-1) ? *(const float4*)(g_xs + (size_t)(m + 1) * ED_ + e)
                             : make_float4(0.f, 0.f, 0.f, 0.f);

    float4 w0 = *(const float4*)(w + (size_t)e * 3);
    float4 w1 = *(const float4*)(w + (size_t)e * 3 + 4);
    float4 w2 = *(const float4*)(w + (size_t)e * 3 + 8);
    float4 bb = *(const float4*)(b + e);

    float r0 = fmaf(prev.x, w0.x, fmaf(cur.x, w0.y, fmaf(nxt.x, w0.z, bb.x)));
    float r1 = fmaf(prev.y, w0.w, fmaf(cur.y, w1.x, fmaf(nxt.y, w1.y, bb.y)));
    float r2 = fmaf(prev.z, w1.z, fmaf(cur.z, w1.w, fmaf(nxt.z, w2.x, bb.z)));
    float r3 = fmaf(prev.w, w2.y, fmaf(cur.w, w2.z, fmaf(nxt.w, w2.w, bb.w)));

    float4 o;
    o.x = r0 * (1.f / (1.f + __expf(-r0)));
    o.y = r1 * (1.f / (1.f + __expf(-r1)));
    o.z = r2 * (1.f / (1.f + __expf(-r2)));
    o.w = r3 * (1.f / (1.f + __expf(-r3)));
    *(float4*)(g_xsc + (size_t)m * ED_ + e) = o;
}

// ---------------- delta = softplus(x_dbl[:, :32] @ dt_proj_w^T + b) ----------------
__global__ void delta_kernel(const float* __restrict__ W,
                             const float* __restrict__ bias)
{
    int mg = blockIdx.x >> 3;
    int e  = ((blockIdx.x & 7) << 8) + threadIdx.x;

    __shared__ float sx[8][32];
    {
        int i  = threadIdx.x;
        int mm = i >> 5, r = i & 31;
        sx[mm][r] = g_xdbl[(size_t)(mg * 8 + mm) * 64 + r];
    }
    __syncthreads();

    float wr[32];
#pragma unroll
    for (int q = 0; q < 8; q++) {
        float4 v = *(const float4*)(W + (size_t)e * 32 + q * 4);
        wr[q * 4 + 0] = v.x; wr[q * 4 + 1] = v.y; wr[q * 4 + 2] = v.z; wr[q * 4 + 3] = v.w;
    }
    float bv = bias[e];

#pragma unroll
    for (int mm = 0; mm < 8; mm++) {
        float acc = bv;
#pragma unroll
        for (int r = 0; r < 32; r++) acc = fmaf(sx[mm][r], wr[r], acc);
        float sp = (acc > 20.f) ? acc : log1pf(__expf(acc));
        g_delta[(size_t)(mg * 8 + mm) * ED_ + e] = sp;
    }
}

// ---------------- fused SSM step ----------------
__global__ void ssm_kernel(const float* __restrict__ h,
                           const float* __restrict__ Dvec,
                           float* __restrict__ hout)
{
    int tid = threadIdx.x;
    int m   = blockIdx.x >> 3;
    int e   = ((blockIdx.x & 7) << 8) + tid;

    __shared__ float sB[N_], sC[N_];
    if (tid < N_)          sB[tid]      = g_xdbl[(size_t)m * 64 + 32 + tid];
    else if (tid < 2*N_)   sC[tid - N_] = g_xdbl[(size_t)m * 64 + 32 + tid];
    __syncthreads();

    size_t me = (size_t)m * ED_ + e;
    float delta = g_delta[me];
    float xs    = g_xsc[me];
    float z     = g_z[me];
    float dx    = delta * xs;

    const float4* h4 = (const float4*)(h + me * N_);
    float4*       o4 = (float4*)(hout + me * N_);
    const float4* a4 = (const float4*)(g_A + (size_t)e * N_);

    float y = 0.f;
#pragma unroll
    for (int q = 0; q < 4; q++) {
        float4 hv = h4[q];
        float4 av = a4[q];
        float4 o;
        o.x = fmaf(__expf(delta * av.x), hv.x, dx * sB[q*4+0]);
        o.y = fmaf(__expf(delta * av.y), hv.y, dx * sB[q*4+1]);
        o.z = fmaf(__expf(delta * av.z), hv.z, dx * sB[q*4+2]);
        o.w = fmaf(__expf(delta * av.w), hv.w, dx * sB[q*4+3]);
        o4[q] = o;
        y = fmaf(o.x, sC[q*4+0], y);
        y = fmaf(o.y, sC[q*4+1], y);
        y = fmaf(o.z, sC[q*4+2], y);
        y = fmaf(o.w, sC[q*4+3], y);
    }
    y = fmaf(Dvec[e], xs, y);
    float sz = z * (1.f / (1.f + __expf(-z)));
    g_y[me] = y * sz;
}

// ---------------- launch ----------------
extern "C" void kernel_launch(void* const* d_in, const int* in_sizes, int n_in,
                              void* d_out, int out_size)
{
    const float* x          = (const float*)d_in[0];
    const float* h          = (const float*)d_in[1];
    const float* in_proj_w  = (const float*)d_in[2];
    const float* conv_w     = (const float*)d_in[3];
    const float* conv_b     = (const float*)d_in[4];
    const float* x_proj_w   = (const float*)d_in[5];
    const float* dt_proj_w  = (const float*)d_in[6];
    const float* dt_proj_b  = (const float*)d_in[7];
    const float* A_log      = (const float*)d_in[8];
    const float* Dvec       = (const float*)d_in[9];
    const float* out_proj_w = (const float*)d_in[10];

    float* out  = (float*)d_out;
    float* hout = out + (size_t)BL_ * D_;

    float* p_xsc = nullptr;
    float* p_y   = nullptr;
    cudaGetSymbolAddress((void**)&p_xsc, g_xsc);
    cudaGetSymbolAddress((void**)&p_y,   g_y);

    const int SMEM_GEMM = 2 * STAGE_B;   // 55296 bytes
    cudaFuncSetAttribute(gemm_mma<0>, cudaFuncAttributeMaxDynamicSharedMemorySize, SMEM_GEMM);
    cudaFuncSetAttribute(gemm_mma<1>, cudaFuncAttributeMaxDynamicSharedMemorySize, SMEM_GEMM);

    // 1. A = -exp(A_log)
    prep_A_kernel<<<(ED_ * N_ + 255) / 256, 256>>>(A_log);

    // 2. in_proj GEMM (3xTF32 mma.sync): (2048x1024) x (4096x1024)^T -> split xs / z
    gemm_mma<1><<<dim3(NPROJ / 128, BL_ / 64), 128, SMEM_GEMM>>>(
        x, in_proj_w, nullptr, NPROJ, D_);

    // 3. depthwise conv + silu
    conv_silu_kernel<<<(BL_ * (ED_ / 4) + 255) / 256, 256>>>(conv_w, conv_b);

    // 4. x_proj GEMM (split-K SIMT) + reduce
    gemm_xproj_sk<<<dim3(1, BL_ / 64, SPLITK), 256>>>(p_xsc, x_proj_w, ED_);
    reduce_xdbl_kernel<<<(BL_ * 64 / 4 + 255) / 256, 256>>>();

    // 5. dt_proj + softplus -> delta
    delta_kernel<<<(BL_ / 8) * 8, 256>>>(dt_proj_w, dt_proj_b);

    // 6. fused SSM (writes h_new to output + y*silu(z) scratch)
    ssm_kernel<<<BL_ * 8, 256>>>(h, Dvec, hout);

    // 7. out_proj GEMM (3xTF32 mma.sync): (2048x2048) x (1024x2048)^T -> out
    gemm_mma<0><<<dim3(D_ / 128, BL_ / 64), 128, SMEM_GEMM>>>(
        p_y, out_proj_w, out, D_, ED_);
}

// round 6
// speedup vs baseline: 1.3213x; 1.2574x over previous
#include <cuda_runtime.h>
#include <cuda_fp16.h>
#include <cstdint>

// Problem constants (fixed shapes)
#define BL_   2048           // B*L = 2*1024
#define L_    1024
#define D_    1024
#define ED_   2048
#define N_    16
#define R_    32
#define NPROJ 4096           // 2*ED
#define SPLITK 16

// ---------------- device scratch (static, no allocation) ----------------
__device__ float g_xs  [BL_ * ED_];
__device__ float g_z   [BL_ * ED_];
__device__ float g_xsc [BL_ * ED_];
__device__ float g_xdbl[BL_ * 64];
__device__ float g_xdbl_part[SPLITK][BL_ * 64];
__device__ float g_delta[BL_ * ED_];
__device__ float g_y   [BL_ * ED_];
__device__ float g_A   [ED_ * N_];

// ---------------- helpers ----------------
__device__ __forceinline__ uint32_t smem_u32(const void* p) {
    uint32_t a;
    asm("{ .reg .u64 t; cvta.to.shared.u64 t, %1; cvt.u32.u64 %0, t; }" : "=r"(a) : "l"(p));
    return a;
}

// split two fp32 into packed fp16 hi + fp16 lo-residual
__device__ __forceinline__ void split_pack(float f0, float f1,
                                           uint32_t& hi, uint32_t& lo) {
    __half h0 = __float2half_rn(f0);
    __half h1 = __float2half_rn(f1);
    float r0 = f0 - __half2float(h0);
    float r1 = f1 - __half2float(h1);
    __half2 H = __halves2half2(h0, h1);
    __half2 L = __halves2half2(__float2half_rn(r0), __float2half_rn(r1));
    hi = *reinterpret_cast<uint32_t*>(&H);
    lo = *reinterpret_cast<uint32_t*>(&L);
}

#define CP16(dst, src) \
    asm volatile("cp.async.cg.shared.global [%0], [%1], 16;" :: "r"(dst), "l"(src))
#define CP_COMMIT() asm volatile("cp.async.commit_group;")
template<int N> __device__ __forceinline__ void cp_wait() {
    asm volatile("cp.async.wait_group %0;" :: "n"(N));
}

#define MMA_F16(c, a0, a1, a2, a3, b0, b1) \
    asm volatile("mma.sync.aligned.m16n8k16.row.col.f32.f16.f16.f32 " \
        "{%0,%1,%2,%3}, {%4,%5,%6,%7}, {%8,%9}, {%0,%1,%2,%3};" \
        : "+f"((c)[0]), "+f"((c)[1]), "+f"((c)[2]), "+f"((c)[3]) \
        : "r"(a0), "r"(a1), "r"(a2), "r"(a3), "r"(b0), "r"(b1))

// ============================================================
// 3xFP16 mma.sync GEMM: C[m][n] = sum_k A[m][k] * B[n][k]
// D += Ahi*Bhi + Ahi*Blo + Alo*Bhi  (hi/lo fp16 split in regs)
// CTA tile 64x128, BK=32, 128 threads = 4 warps (2m x 2n),
// warp tile 32x64. fp32 single-copy SMEM (SROW=36 padding),
// cp.async double buffer.
// EPI 0: C[m*Nout + n]
// EPI 1: n0<2048 -> g_xs ; else -> g_z (col n-2048)
// ============================================================
#define SROW 36                       // padded row, floats
#define ATF_A (64 * SROW)             // A tile floats (2304)
#define ATF_B (128 * SROW)            // B tile floats (4608)
#define STAGE_F (ATF_A + ATF_B)       // 6912 floats
#define STAGE_B (STAGE_F * 4)         // 27648 bytes

template<int EPI>
__global__ void __launch_bounds__(128, 2)
gemm_mma(const float* __restrict__ A, const float* __restrict__ B,
         float* __restrict__ C, int Nout, int K)
{
    extern __shared__ float sm[];
    const int tid  = threadIdx.x;
    const int wid  = tid >> 5;           // 0..3
    const int lane = tid & 31;
    const int gq   = lane >> 2;          // 0..7
    const int tig  = lane & 3;           // 0..3
    const int m0   = blockIdx.y * 64;
    const int n0   = blockIdx.x * 128;
    const int wm   = (wid >> 1) * 32;    // warp m offset (0/32)
    const int wn   = (wid & 1) * 64;     // warp n offset (0/64)
    const int NC   = K >> 5;

    float acc[2][8][4];
#pragma unroll
    for (int i = 0; i < 2; i++)
#pragma unroll
        for (int j = 0; j < 8; j++)
#pragma unroll
            for (int q = 0; q < 4; q++) acc[i][j][q] = 0.f;

    const uint32_t sbase = smem_u32(sm);
    const int lr  = tid >> 3;            // 0..15 loader row
    const int lc4 = (tid & 7) << 2;      // loader col (floats)
    const float* ga = A + (size_t)(m0 + lr) * K + lc4;
    const float* gb = B + (size_t)(n0 + lr) * K + lc4;
    const uint32_t s_off = (uint32_t)(lr * SROW + lc4) * 4;

    // ---- prologue: issue chunks 0 and 1 ----
#pragma unroll
    for (int c = 0; c < 2; c++) {
        uint32_t sa  = sbase + c * STAGE_B + s_off;
        uint32_t sbb = sa + ATF_A * 4;
        const float* pa = ga + c * 32;
        const float* pb = gb + c * 32;
#pragma unroll
        for (int i = 0; i < 4; i++)      // A: 64 rows
            CP16(sa + i * 16 * SROW * 4, pa + (size_t)(i * 16) * K);
#pragma unroll
        for (int i = 0; i < 8; i++)      // B: 128 rows
            CP16(sbb + i * 16 * SROW * 4, pb + (size_t)(i * 16) * K);
        CP_COMMIT();
    }
    cp_wait<1>();
    __syncthreads();

    for (int c = 0; c < NC; c++) {
        const int buf = c & 1;
        const float* As = sm + buf * STAGE_F;
        const float* Bs = As + ATF_A;

#pragma unroll
        for (int ks = 0; ks < 2; ks++) {      // two k16 steps per chunk
            // B fragments for 8 n-tiles (hi/lo), m16n8k16 layout:
            // b0 = {B[k=2tig][n=gq], B[k=2tig+1][n=gq]}, b1 = same at k+8
            uint32_t bhi[8][2], blo[8][2];
#pragma unroll
            for (int nt = 0; nt < 8; nt++) {
                const float* bp = Bs + (wn + 8 * nt + gq) * SROW + ks * 16;
                float2 p0 = *(const float2*)(bp + 2 * tig);
                float2 p1 = *(const float2*)(bp + 2 * tig + 8);
                split_pack(p0.x, p0.y, bhi[nt][0], blo[nt][0]);
                split_pack(p1.x, p1.y, bhi[nt][1], blo[nt][1]);
            }
#pragma unroll
            for (int mt = 0; mt < 2; mt++) {
                // A fragment: a0={A[gq][2tig..+1]}, a1={A[gq+8][..]},
                //             a2={A[gq][2tig+8..]}, a3={A[gq+8][2tig+8..]}
                const float* ap = As + (wm + 16 * mt + gq) * SROW + ks * 16;
                float2 q0 = *(const float2*)(ap + 2 * tig);
                float2 q1 = *(const float2*)(ap + 8 * SROW + 2 * tig);
                float2 q2 = *(const float2*)(ap + 2 * tig + 8);
                float2 q3 = *(const float2*)(ap + 8 * SROW + 2 * tig + 8);
                uint32_t ah[4], al[4];
                split_pack(q0.x, q0.y, ah[0], al[0]);
                split_pack(q1.x, q1.y, ah[1], al[1]);
                split_pack(q2.x, q2.y, ah[2], al[2]);
                split_pack(q3.x, q3.y, ah[3], al[3]);
#pragma unroll
                for (int nt = 0; nt < 8; nt++) {
                    MMA_F16(acc[mt][nt], ah[0], ah[1], ah[2], ah[3], bhi[nt][0], bhi[nt][1]);
                    MMA_F16(acc[mt][nt], ah[0], ah[1], ah[2], ah[3], blo[nt][0], blo[nt][1]);
                    MMA_F16(acc[mt][nt], al[0], al[1], al[2], al[3], bhi[nt][0], bhi[nt][1]);
                }
            }
        }
        __syncthreads();   // all warps done reading buf

        if (c + 2 < NC) {
            uint32_t sa  = sbase + buf * STAGE_B + s_off;
            uint32_t sbb = sa + ATF_A * 4;
            const float* pa = ga + (c + 2) * 32;
            const float* pb = gb + (c + 2) * 32;
#pragma unroll
            for (int i = 0; i < 4; i++)
                CP16(sa + i * 16 * SROW * 4, pa + (size_t)(i * 16) * K);
#pragma unroll
            for (int i = 0; i < 8; i++)
                CP16(sbb + i * 16 * SROW * 4, pb + (size_t)(i * 16) * K);
            CP_COMMIT();
            cp_wait<1>();
        } else {
            cp_wait<0>();
        }
        __syncthreads();
    }

    // ---- epilogue ----
    float* dst;
    int ld, ncol0;
    if (EPI == 1) {
        if (n0 < ED_) { dst = g_xs; ncol0 = n0; }
        else          { dst = g_z;  ncol0 = n0 - ED_; }
        ld = ED_;
    } else {
        dst = C; ncol0 = n0; ld = Nout;
    }
#pragma unroll
    for (int mt = 0; mt < 2; mt++) {
        const int m = m0 + wm + 16 * mt + gq;
#pragma unroll
        for (int nt = 0; nt < 8; nt++) {
            const int n = ncol0 + wn + 8 * nt + 2 * tig;
            float2 v0 = make_float2(acc[mt][nt][0], acc[mt][nt][1]);
            float2 v1 = make_float2(acc[mt][nt][2], acc[mt][nt][3]);
            *(float2*)(dst + (size_t)m * ld + n)       = v0;
            *(float2*)(dst + (size_t)(m + 8) * ld + n) = v1;
        }
    }
}

// ---------------- tiny precompute: A = -exp(A_log) ----------------
__global__ void prep_A_kernel(const float* __restrict__ A_log) {
    int i = blockIdx.x * blockDim.x + threadIdx.x;
    if (i < ED_ * N_) g_A[i] = -expf(A_log[i]);
}

// ---------------- split-K SIMT GEMM for x_proj ----------------
// grid (1, M/64, SPLITK); block 256. K-slice = K/SPLITK = 128.
__global__ void __launch_bounds__(256)
gemm_xproj_sk(const float* __restrict__ A, const float* __restrict__ B, int K)
{
    constexpr int BM = 64, BN = 64, BK = 16, TM = 4, TN = 4;
    __shared__ float As[BK * BM];
    __shared__ float Bs[BK * BN];

    const int t  = threadIdx.x;
    const int m0 = blockIdx.y * BM;
    const int z  = blockIdx.z;
    const int KS = K / SPLITK;
    const int kbeg = z * KS;
    const int tr = t / (BN / TN);
    const int tc = t % (BN / TN);

    float acc[TM][TN];
#pragma unroll
    for (int i = 0; i < TM; i++)
#pragma unroll
        for (int j = 0; j < TN; j++) acc[i][j] = 0.f;

    for (int k0 = kbeg; k0 < kbeg + KS; k0 += BK) {
        {
            int row = t / (BK / 4);
            int cc  = t % (BK / 4);
            float4 v = *(const float4*)(A + (size_t)(m0 + row) * K + k0 + cc * 4);
            As[(cc * 4 + 0) * BM + row] = v.x;
            As[(cc * 4 + 1) * BM + row] = v.y;
            As[(cc * 4 + 2) * BM + row] = v.z;
            As[(cc * 4 + 3) * BM + row] = v.w;
            float4 w = *(const float4*)(B + (size_t)row * K + k0 + cc * 4);
            Bs[(cc * 4 + 0) * BN + row] = w.x;
            Bs[(cc * 4 + 1) * BN + row] = w.y;
            Bs[(cc * 4 + 2) * BN + row] = w.z;
            Bs[(cc * 4 + 3) * BN + row] = w.w;
        }
        __syncthreads();
#pragma unroll
        for (int kk = 0; kk < BK; kk++) {
            float af[TM], bf[TN];
#pragma unroll
            for (int i = 0; i < TM; i++) af[i] = As[kk * BM + tr * TM + i];
#pragma unroll
            for (int j = 0; j < TN; j++) bf[j] = Bs[kk * BN + tc * TN + j];
#pragma unroll
            for (int i = 0; i < TM; i++)
#pragma unroll
                for (int j = 0; j < TN; j++)
                    acc[i][j] = fmaf(af[i], bf[j], acc[i][j]);
        }
        __syncthreads();
    }
#pragma unroll
    for (int i = 0; i < TM; i++) {
        int m = m0 + tr * TM + i;
#pragma unroll
        for (int j = 0; j < TN; j++) {
            int n = tc * TN + j;
            g_xdbl_part[z][(size_t)m * 64 + n] = acc[i][j];
        }
    }
}

__global__ void reduce_xdbl_kernel() {
    int i = blockIdx.x * blockDim.x + threadIdx.x;
    if (i >= BL_ * 64 / 4) return;
    float4 s = make_float4(0.f, 0.f, 0.f, 0.f);
#pragma unroll
    for (int z = 0; z < SPLITK; z++) {
        float4 v = *((const float4*)g_xdbl_part[z] + i);
        s.x += v.x; s.y += v.y; s.z += v.z; s.w += v.w;
    }
    *((float4*)g_xdbl + i) = s;
}

// ---------------- depthwise conv1d (k=3, pad 1) + silu ----------------
__global__ void conv_silu_kernel(const float* __restrict__ w,
                                 const float* __restrict__ b)
{
    int idx = blockIdx.x * blockDim.x + threadIdx.x;
    if (idx >= BL_ * (ED_ / 4)) return;
    int m  = idx >> 9;
    int e4 = idx & 511;
    int e  = e4 * 4;
    int l  = m & (L_ - 1);

    float4 cur  = *(const float4*)(g_xs + (size_t)m * ED_ + e);
    float4 prev = (l > 0)    ? *(const float4*)(g_xs + (size_t)(m - 1) * ED_ + e)
                             : make_float4(0.f, 0.f, 0.f, 0.f);
    float4 nxt  = (l < L_-1) ? *(const float4*)(g_xs + (size_t)(m + 1) * ED_ + e)
                             : make_float4(0.f, 0.f, 0.f, 0.f);

    float4 w0 = *(const float4*)(w + (size_t)e * 3);
    float4 w1 = *(const float4*)(w + (size_t)e * 3 + 4);
    float4 w2 = *(const float4*)(w + (size_t)e * 3 + 8);
    float4 bb = *(const float4*)(b + e);

    float r0 = fmaf(prev.x, w0.x, fmaf(cur.x, w0.y, fmaf(nxt.x, w0.z, bb.x)));
    float r1 = fmaf(prev.y, w0.w, fmaf(cur.y, w1.x, fmaf(nxt.y, w1.y, bb.y)));
    float r2 = fmaf(prev.z, w1.z, fmaf(cur.z, w1.w, fmaf(nxt.z, w2.x, bb.z)));
    float r3 = fmaf(prev.w, w2.y, fmaf(cur.w, w2.z, fmaf(nxt.w, w2.w, bb.w)));

    float4 o;
    o.x = r0 * (1.f / (1.f + __expf(-r0)));
    o.y = r1 * (1.f / (1.f + __expf(-r1)));
    o.z = r2 * (1.f / (1.f + __expf(-r2)));
    o.w = r3 * (1.f / (1.f + __expf(-r3)));
    *(float4*)(g_xsc + (size_t)m * ED_ + e) = o;
}

// ---------------- delta = softplus(x_dbl[:, :32] @ dt_proj_w^T + b) ----------------
__global__ void delta_kernel(const float* __restrict__ W,
                             const float* __restrict__ bias)
{
    int mg = blockIdx.x >> 3;
    int e  = ((blockIdx.x & 7) << 8) + threadIdx.x;

    __shared__ float sx[8][32];
    {
        int i  = threadIdx.x;
        int mm = i >> 5, r = i & 31;
        sx[mm][r] = g_xdbl[(size_t)(mg * 8 + mm) * 64 + r];
    }
    __syncthreads();

    float wr[32];
#pragma unroll
    for (int q = 0; q < 8; q++) {
        float4 v = *(const float4*)(W + (size_t)e * 32 + q * 4);
        wr[q * 4 + 0] = v.x; wr[q * 4 + 1] = v.y; wr[q * 4 + 2] = v.z; wr[q * 4 + 3] = v.w;
    }
    float bv = bias[e];

#pragma unroll
    for (int mm = 0; mm < 8; mm++) {
        float acc = bv;
#pragma unroll
        for (int r = 0; r < 32; r++) acc = fmaf(sx[mm][r], wr[r], acc);
        float sp = (acc > 20.f) ? acc : log1pf(__expf(acc));
        g_delta[(size_t)(mg * 8 + mm) * ED_ + e] = sp;
    }
}

// ---------------- fused SSM step ----------------
__global__ void ssm_kernel(const float* __restrict__ h,
                           const float* __restrict__ Dvec,
                           float* __restrict__ hout)
{
    int tid = threadIdx.x;
    int m   = blockIdx.x >> 3;
    int e   = ((blockIdx.x & 7) << 8) + tid;

    __shared__ float sB[N_], sC[N_];
    if (tid < N_)          sB[tid]      = g_xdbl[(size_t)m * 64 + 32 + tid];
    else if (tid < 2*N_)   sC[tid - N_] = g_xdbl[(size_t)m * 64 + 32 + tid];
    __syncthreads();

    size_t me = (size_t)m * ED_ + e;
    float delta = g_delta[me];
    float xs    = g_xsc[me];
    float z     = g_z[me];
    float dx    = delta * xs;

    const float4* h4 = (const float4*)(h + me * N_);
    float4*       o4 = (float4*)(hout + me * N_);
    const float4* a4 = (const float4*)(g_A + (size_t)e * N_);

    float y = 0.f;
#pragma unroll
    for (int q = 0; q < 4; q++) {
        float4 hv = h4[q];
        float4 av = a4[q];
        float4 o;
        o.x = fmaf(__expf(delta * av.x), hv.x, dx * sB[q*4+0]);
        o.y = fmaf(__expf(delta * av.y), hv.y, dx * sB[q*4+1]);
        o.z = fmaf(__expf(delta * av.z), hv.z, dx * sB[q*4+2]);
        o.w = fmaf(__expf(delta * av.w), hv.w, dx * sB[q*4+3]);
        o4[q] = o;
        y = fmaf(o.x, sC[q*4+0], y);
        y = fmaf(o.y, sC[q*4+1], y);
        y = fmaf(o.z, sC[q*4+2], y);
        y = fmaf(o.w, sC[q*4+3], y);
    }
    y = fmaf(Dvec[e], xs, y);
    float sz = z * (1.f / (1.f + __expf(-z)));
    g_y[me] = y * sz;
}

// ---------------- launch ----------------
extern "C" void kernel_launch(void* const* d_in, const int* in_sizes, int n_in,
                              void* d_out, int out_size)
{
    const float* x          = (const float*)d_in[0];
    const float* h          = (const float*)d_in[1];
    const float* in_proj_w  = (const float*)d_in[2];
    const float* conv_w     = (const float*)d_in[3];
    const float* conv_b     = (const float*)d_in[4];
    const float* x_proj_w   = (const float*)d_in[5];
    const float* dt_proj_w  = (const float*)d_in[6];
    const float* dt_proj_b  = (const float*)d_in[7];
    const float* A_log      = (const float*)d_in[8];
    const float* Dvec       = (const float*)d_in[9];
    const float* out_proj_w = (const float*)d_in[10];

    float* out  = (float*)d_out;
    float* hout = out + (size_t)BL_ * D_;

    float* p_xsc = nullptr;
    float* p_y   = nullptr;
    cudaGetSymbolAddress((void**)&p_xsc, g_xsc);
    cudaGetSymbolAddress((void**)&p_y,   g_y);

    const int SMEM_GEMM = 2 * STAGE_B;   // 55296 bytes
    cudaFuncSetAttribute(gemm_mma<0>, cudaFuncAttributeMaxDynamicSharedMemorySize, SMEM_GEMM);
    cudaFuncSetAttribute(gemm_mma<1>, cudaFuncAttributeMaxDynamicSharedMemorySize, SMEM_GEMM);

    // 1. A = -exp(A_log)
    prep_A_kernel<<<(ED_ * N_ + 255) / 256, 256>>>(A_log);

    // 2. in_proj GEMM (3xFP16 mma.sync): (2048x1024) x (4096x1024)^T -> split xs / z
    gemm_mma<1><<<dim3(NPROJ / 128, BL_ / 64), 128, SMEM_GEMM>>>(
        x, in_proj_w, nullptr, NPROJ, D_);

    // 3. depthwise conv + silu
    conv_silu_kernel<<<(BL_ * (ED_ / 4) + 255) / 256, 256>>>(conv_w, conv_b);

    // 4. x_proj GEMM (split-K SIMT) + reduce
    gemm_xproj_sk<<<dim3(1, BL_ / 64, SPLITK), 256>>>(p_xsc, x_proj_w, ED_);
    reduce_xdbl_kernel<<<(BL_ * 64 / 4 + 255) / 256, 256>>>();

    // 5. dt_proj + softplus -> delta
    delta_kernel<<<(BL_ / 8) * 8, 256>>>(dt_proj_w, dt_proj_b);

    // 6. fused SSM (writes h_new to output + y*silu(z) scratch)
    ssm_kernel<<<BL_ * 8, 256>>>(h, Dvec, hout);

    // 7. out_proj GEMM (3xFP16 mma.sync): (2048x2048) x (1024x2048)^T -> out
    gemm_mma<0><<<dim3(D_ / 128, BL_ / 64), 128, SMEM_GEMM>>>(
        p_y, out_proj_w, out, D_, ED_);
}

// round 7
// speedup vs baseline: 1.4275x; 1.0804x over previous
#include <cuda_runtime.h>
#include <cuda_fp16.h>
#include <cstdint>

// Problem constants (fixed shapes)
#define BL_   2048           // B*L = 2*1024
#define L_    1024
#define D_    1024
#define ED_   2048
#define N_    16
#define R_    32
#define NPROJ 4096           // 2*ED
#define SPLITK 16

// ---------------- device scratch (static, no allocation) ----------------
__device__ float g_xs  [BL_ * ED_];
__device__ float g_z   [BL_ * ED_];
__device__ float g_xsc [BL_ * ED_];
__device__ float g_xdbl[BL_ * 64];
__device__ float g_xdbl_part[SPLITK][BL_ * 64];
__device__ float g_delta[BL_ * ED_];
__device__ float g_y   [BL_ * ED_];
__device__ float g_A   [ED_ * N_];

// ---------------- helpers ----------------
// split float4 (4 consecutive k) into packed half2 hi pair + lo pair
__device__ __forceinline__ void split4(float4 v, uint2& hi, uint2& lo) {
    __half2 h0 = __floats2half2_rn(v.x, v.y);
    __half2 h1 = __floats2half2_rn(v.z, v.w);
    float2 f0 = __half22float2(h0);
    float2 f1 = __half22float2(h1);
    __half2 l0 = __floats2half2_rn(v.x - f0.x, v.y - f0.y);
    __half2 l1 = __floats2half2_rn(v.z - f1.x, v.w - f1.y);
    hi.x = *reinterpret_cast<uint32_t*>(&h0);
    hi.y = *reinterpret_cast<uint32_t*>(&h1);
    lo.x = *reinterpret_cast<uint32_t*>(&l0);
    lo.y = *reinterpret_cast<uint32_t*>(&l1);
}

#define MMA_F16(c, a0, a1, a2, a3, b0, b1) \
    asm volatile("mma.sync.aligned.m16n8k16.row.col.f32.f16.f16.f32 " \
        "{%0,%1,%2,%3}, {%4,%5,%6,%7}, {%8,%9}, {%0,%1,%2,%3};" \
        : "+f"((c)[0]), "+f"((c)[1]), "+f"((c)[2]), "+f"((c)[3]) \
        : "r"(a0), "r"(a1), "r"(a2), "r"(a3), "r"(b0), "r"(b1))

// ============================================================
// 3xFP16 mma.sync GEMM, hi/lo split ONCE at tile load.
// C[m][n] = sum_k A[m][k]*B[n][k]
// CTA 64x128, BK=32, 128 threads = 4 warps (2m x 2n), warp 32x64.
// SMEM: fp16 hi/lo tiles (PADH=40 halves/row -> conflict-free frags),
// register-double-buffered LDG->cvt->STS producer.
// EPI 0: C[m*Nout+n];  EPI 1: split to g_xs / g_z.
// ============================================================
#define PADH 40                          // halves per row (80 B)
#define AHI_OFF 0
#define ALO_OFF 5120                     // 64*80
#define BHI_OFF 10240
#define BLO_OFF 20480                    // +128*80
#define STAGE_B 30720                    // bytes per stage

template<int EPI>
__global__ void __launch_bounds__(128, 2)
gemm_mma(const float* __restrict__ A, const float* __restrict__ B,
         float* __restrict__ C, int Nout, int K)
{
    extern __shared__ char smem[];
    const int tid  = threadIdx.x;
    const int wid  = tid >> 5;           // 0..3
    const int lane = tid & 31;
    const int gq   = lane >> 2;          // 0..7
    const int tig  = lane & 3;           // 0..3
    const int m0   = blockIdx.y * 64;
    const int n0   = blockIdx.x * 128;
    const int wm   = (wid >> 1) * 32;    // warp m offset
    const int wn   = (wid & 1) * 64;     // warp n offset
    const int NC   = K >> 5;

    float acc[2][8][4];
#pragma unroll
    for (int i = 0; i < 2; i++)
#pragma unroll
        for (int j = 0; j < 8; j++)
#pragma unroll
            for (int q = 0; q < 4; q++) acc[i][j][q] = 0.f;

    // loader mapping: 16 rows x 8 col-quads
    const int lr  = tid >> 3;            // 0..15
    const int lc4 = (tid & 7) << 2;      // 0,4,...,28
    const float* ga = A + (size_t)(m0 + lr) * K + lc4;
    const float* gb = B + (size_t)(n0 + lr) * K + lc4;
    const uint32_t sA = (uint32_t)(lr * PADH + lc4) * 2;  // byte offset in A tiles
    const uint32_t sB = sA;                                // same shape mapping for B

    float4 pfA[4], pfB[8];

    auto ldg_chunk = [&](int c) {
        const float* pa = ga + c * 32;
        const float* pb = gb + c * 32;
#pragma unroll
        for (int i = 0; i < 4; i++) pfA[i] = *(const float4*)(pa + (size_t)(i * 16) * K);
#pragma unroll
        for (int i = 0; i < 8; i++) pfB[i] = *(const float4*)(pb + (size_t)(i * 16) * K);
    };
    auto sts_chunk = [&](int buf) {
        char* st = smem + buf * STAGE_B;
#pragma unroll
        for (int i = 0; i < 4; i++) {
            uint2 hi, lo; split4(pfA[i], hi, lo);
            uint32_t o = sA + (uint32_t)(i * 16 * PADH) * 2;
            *(uint2*)(st + AHI_OFF + o) = hi;
            *(uint2*)(st + ALO_OFF + o) = lo;
        }
#pragma unroll
        for (int i = 0; i < 8; i++) {
            uint2 hi, lo; split4(pfB[i], hi, lo);
            uint32_t o = sB + (uint32_t)(i * 16 * PADH) * 2;
            *(uint2*)(st + BHI_OFF + o) = hi;
            *(uint2*)(st + BLO_OFF + o) = lo;
        }
    };

    // ---- prologue ----
    ldg_chunk(0);
    sts_chunk(0);
    if (NC > 1) ldg_chunk(1);
    __syncthreads();

    for (int c = 0; c < NC; c++) {
        const int buf = c & 1;
        if (c + 1 < NC) sts_chunk((c + 1) & 1);   // prev contents consumed in iter c-1
        if (c + 2 < NC) ldg_chunk(c + 2);

        const char* Ahi = smem + buf * STAGE_B + AHI_OFF;
        const char* Alo = smem + buf * STAGE_B + ALO_OFF;
        const char* Bhi = smem + buf * STAGE_B + BHI_OFF;
        const char* Blo = smem + buf * STAGE_B + BLO_OFF;

#pragma unroll
        for (int ks = 0; ks < 2; ks++) {
            uint32_t bh[8][2], bl[8][2];
#pragma unroll
            for (int nt = 0; nt < 8; nt++) {
                uint32_t ro = (uint32_t)((wn + 8 * nt + gq) * PADH + ks * 16 + 2 * tig) * 2;
                bh[nt][0] = *(const uint32_t*)(Bhi + ro);
                bh[nt][1] = *(const uint32_t*)(Bhi + ro + 16);
                bl[nt][0] = *(const uint32_t*)(Blo + ro);
                bl[nt][1] = *(const uint32_t*)(Blo + ro + 16);
            }
#pragma unroll
            for (int mt = 0; mt < 2; mt++) {
                uint32_t ro = (uint32_t)((wm + 16 * mt + gq) * PADH + ks * 16 + 2 * tig) * 2;
                uint32_t ah[4], al[4];
                ah[0] = *(const uint32_t*)(Ahi + ro);
                ah[1] = *(const uint32_t*)(Ahi + ro + 8 * PADH * 2);
                ah[2] = *(const uint32_t*)(Ahi + ro + 16);
                ah[3] = *(const uint32_t*)(Ahi + ro + 8 * PADH * 2 + 16);
                al[0] = *(const uint32_t*)(Alo + ro);
                al[1] = *(const uint32_t*)(Alo + ro + 8 * PADH * 2);
                al[2] = *(const uint32_t*)(Alo + ro + 16);
                al[3] = *(const uint32_t*)(Alo + ro + 8 * PADH * 2 + 16);
#pragma unroll
                for (int nt = 0; nt < 8; nt++) {
                    MMA_F16(acc[mt][nt], ah[0], ah[1], ah[2], ah[3], bh[nt][0], bh[nt][1]);
                    MMA_F16(acc[mt][nt], ah[0], ah[1], ah[2], ah[3], bl[nt][0], bl[nt][1]);
                    MMA_F16(acc[mt][nt], al[0], al[1], al[2], al[3], bh[nt][0], bh[nt][1]);
                }
            }
        }
        __syncthreads();
    }

    // ---- epilogue ----
    float* dst;
    int ld, ncol0;
    if (EPI == 1) {
        if (n0 < ED_) { dst = g_xs; ncol0 = n0; }
        else          { dst = g_z;  ncol0 = n0 - ED_; }
        ld = ED_;
    } else {
        dst = C; ncol0 = n0; ld = Nout;
    }
#pragma unroll
    for (int mt = 0; mt < 2; mt++) {
        const int m = m0 + wm + 16 * mt + gq;
#pragma unroll
        for (int nt = 0; nt < 8; nt++) {
            const int n = ncol0 + wn + 8 * nt + 2 * tig;
            float2 v0 = make_float2(acc[mt][nt][0], acc[mt][nt][1]);
            float2 v1 = make_float2(acc[mt][nt][2], acc[mt][nt][3]);
            *(float2*)(dst + (size_t)m * ld + n)       = v0;
            *(float2*)(dst + (size_t)(m + 8) * ld + n) = v1;
        }
    }
}

// ---------------- tiny precompute: A = -exp(A_log) ----------------
__global__ void prep_A_kernel(const float* __restrict__ A_log) {
    int i = blockIdx.x * blockDim.x + threadIdx.x;
    if (i < ED_ * N_) g_A[i] = -expf(A_log[i]);
}

// ---------------- split-K SIMT GEMM for x_proj ----------------
__global__ void __launch_bounds__(256)
gemm_xproj_sk(const float* __restrict__ A, const float* __restrict__ B, int K)
{
    constexpr int BM = 64, BN = 64, BK = 16, TM = 4, TN = 4;
    __shared__ float As[BK * BM];
    __shared__ float Bs[BK * BN];

    const int t  = threadIdx.x;
    const int m0 = blockIdx.y * BM;
    const int z  = blockIdx.z;
    const int KS = K / SPLITK;
    const int kbeg = z * KS;
    const int tr = t / (BN / TN);
    const int tc = t % (BN / TN);

    float acc[TM][TN];
#pragma unroll
    for (int i = 0; i < TM; i++)
#pragma unroll
        for (int j = 0; j < TN; j++) acc[i][j] = 0.f;

    for (int k0 = kbeg; k0 < kbeg + KS; k0 += BK) {
        {
            int row = t / (BK / 4);
            int cc  = t % (BK / 4);
            float4 v = *(const float4*)(A + (size_t)(m0 + row) * K + k0 + cc * 4);
            As[(cc * 4 + 0) * BM + row] = v.x;
            As[(cc * 4 + 1) * BM + row] = v.y;
            As[(cc * 4 + 2) * BM + row] = v.z;
            As[(cc * 4 + 3) * BM + row] = v.w;
            float4 w = *(const float4*)(B + (size_t)row * K + k0 + cc * 4);
            Bs[(cc * 4 + 0) * BN + row] = w.x;
            Bs[(cc * 4 + 1) * BN + row] = w.y;
            Bs[(cc * 4 + 2) * BN + row] = w.z;
            Bs[(cc * 4 + 3) * BN + row] = w.w;
        }
        __syncthreads();
#pragma unroll
        for (int kk = 0; kk < BK; kk++) {
            float af[TM], bf[TN];
#pragma unroll
            for (int i = 0; i < TM; i++) af[i] = As[kk * BM + tr * TM + i];
#pragma unroll
            for (int j = 0; j < TN; j++) bf[j] = Bs[kk * BN + tc * TN + j];
#pragma unroll
            for (int i = 0; i < TM; i++)
#pragma unroll
                for (int j = 0; j < TN; j++)
                    acc[i][j] = fmaf(af[i], bf[j], acc[i][j]);
        }
        __syncthreads();
    }
#pragma unroll
    for (int i = 0; i < TM; i++) {
        int m = m0 + tr * TM + i;
#pragma unroll
        for (int j = 0; j < TN; j++) {
            int n = tc * TN + j;
            g_xdbl_part[z][(size_t)m * 64 + n] = acc[i][j];
        }
    }
}

__global__ void reduce_xdbl_kernel() {
    int i = blockIdx.x * blockDim.x + threadIdx.x;
    if (i >= BL_ * 64 / 4) return;
    float4 s = make_float4(0.f, 0.f, 0.f, 0.f);
#pragma unroll
    for (int z = 0; z < SPLITK; z++) {
        float4 v = *((const float4*)g_xdbl_part[z] + i);
        s.x += v.x; s.y += v.y; s.z += v.z; s.w += v.w;
    }
    *((float4*)g_xdbl + i) = s;
}

// ---------------- depthwise conv1d (k=3, pad 1) + silu ----------------
__global__ void conv_silu_kernel(const float* __restrict__ w,
                                 const float* __restrict__ b)
{
    int idx = blockIdx.x * blockDim.x + threadIdx.x;
    if (idx >= BL_ * (ED_ / 4)) return;
    int m  = idx >> 9;
    int e4 = idx & 511;
    int e  = e4 * 4;
    int l  = m & (L_ - 1);

    float4 cur  = *(const float4*)(g_xs + (size_t)m * ED_ + e);
    float4 prev = (l > 0)    ? *(const float4*)(g_xs + (size_t)(m - 1) * ED_ + e)
                             : make_float4(0.f, 0.f, 0.f, 0.f);
    float4 nxt  = (l < L_-1) ? *(const float4*)(g_xs + (size_t)(m + 1) * ED_ + e)
                             : make_float4(0.f, 0.f, 0.f, 0.f);

    float4 w0 = *(const float4*)(w + (size_t)e * 3);
    float4 w1 = *(const float4*)(w + (size_t)e * 3 + 4);
    float4 w2 = *(const float4*)(w + (size_t)e * 3 + 8);
    float4 bb = *(const float4*)(b + e);

    float r0 = fmaf(prev.x, w0.x, fmaf(cur.x, w0.y, fmaf(nxt.x, w0.z, bb.x)));
    float r1 = fmaf(prev.y, w0.w, fmaf(cur.y, w1.x, fmaf(nxt.y, w1.y, bb.y)));
    float r2 = fmaf(prev.z, w1.z, fmaf(cur.z, w1.w, fmaf(nxt.z, w2.x, bb.z)));
    float r3 = fmaf(prev.w, w2.y, fmaf(cur.w, w2.z, fmaf(nxt.w, w2.w, bb.w)));

    float4 o;
    o.x = r0 * (1.f / (1.f + __expf(-r0)));
    o.y = r1 * (1.f / (1.f + __expf(-r1)));
    o.z = r2 * (1.f / (1.f + __expf(-r2)));
    o.w = r3 * (1.f / (1.f + __expf(-r3)));
    *(float4*)(g_xsc + (size_t)m * ED_ + e) = o;
}

// ---------------- delta = softplus(x_dbl[:, :32] @ dt_proj_w^T + b) ----------------
__global__ void delta_kernel(const float* __restrict__ W,
                             const float* __restrict__ bias)
{
    int mg = blockIdx.x >> 3;
    int e  = ((blockIdx.x & 7) << 8) + threadIdx.x;

    __shared__ float sx[8][32];
    {
        int i  = threadIdx.x;
        int mm = i >> 5, r = i & 31;
        sx[mm][r] = g_xdbl[(size_t)(mg * 8 + mm) * 64 + r];
    }
    __syncthreads();

    float wr[32];
#pragma unroll
    for (int q = 0; q < 8; q++) {
        float4 v = *(const float4*)(W + (size_t)e * 32 + q * 4);
        wr[q * 4 + 0] = v.x; wr[q * 4 + 1] = v.y; wr[q * 4 + 2] = v.z; wr[q * 4 + 3] = v.w;
    }
    float bv = bias[e];

#pragma unroll
    for (int mm = 0; mm < 8; mm++) {
        float acc = bv;
#pragma unroll
        for (int r = 0; r < 32; r++) acc = fmaf(sx[mm][r], wr[r], acc);
        float sp = (acc > 20.f) ? acc : log1pf(__expf(acc));
        g_delta[(size_t)(mg * 8 + mm) * ED_ + e] = sp;
    }
}

// ---------------- fused SSM step ----------------
__global__ void ssm_kernel(const float* __restrict__ h,
                           const float* __restrict__ Dvec,
                           float* __restrict__ hout)
{
    int tid = threadIdx.x;
    int m   = blockIdx.x >> 3;
    int e   = ((blockIdx.x & 7) << 8) + tid;

    __shared__ float sB[N_], sC[N_];
    if (tid < N_)          sB[tid]      = g_xdbl[(size_t)m * 64 + 32 + tid];
    else if (tid < 2*N_)   sC[tid - N_] = g_xdbl[(size_t)m * 64 + 32 + tid];
    __syncthreads();

    size_t me = (size_t)m * ED_ + e;
    float delta = g_delta[me];
    float xs    = g_xsc[me];
    float z     = g_z[me];
    float dx    = delta * xs;

    const float4* h4 = (const float4*)(h + me * N_);
    float4*       o4 = (float4*)(hout + me * N_);
    const float4* a4 = (const float4*)(g_A + (size_t)e * N_);

    float y = 0.f;
#pragma unroll
    for (int q = 0; q < 4; q++) {
        float4 hv = h4[q];
        float4 av = a4[q];
        float4 o;
        o.x = fmaf(__expf(delta * av.x), hv.x, dx * sB[q*4+0]);
        o.y = fmaf(__expf(delta * av.y), hv.y, dx * sB[q*4+1]);
        o.z = fmaf(__expf(delta * av.z), hv.z, dx * sB[q*4+2]);
        o.w = fmaf(__expf(delta * av.w), hv.w, dx * sB[q*4+3]);
        o4[q] = o;
        y = fmaf(o.x, sC[q*4+0], y);
        y = fmaf(o.y, sC[q*4+1], y);
        y = fmaf(o.z, sC[q*4+2], y);
        y = fmaf(o.w, sC[q*4+3], y);
    }
    y = fmaf(Dvec[e], xs, y);
    float sz = z * (1.f / (1.f + __expf(-z)));
    g_y[me] = y * sz;
}

// ---------------- launch ----------------
extern "C" void kernel_launch(void* const* d_in, const int* in_sizes, int n_in,
                              void* d_out, int out_size)
{
    const float* x          = (const float*)d_in[0];
    const float* h          = (const float*)d_in[1];
    const float* in_proj_w  = (const float*)d_in[2];
    const float* conv_w     = (const float*)d_in[3];
    const float* conv_b     = (const float*)d_in[4];
    const float* x_proj_w   = (const float*)d_in[5];
    const float* dt_proj_w  = (const float*)d_in[6];
    const float* dt_proj_b  = (const float*)d_in[7];
    const float* A_log      = (const float*)d_in[8];
    const float* Dvec       = (const float*)d_in[9];
    const float* out_proj_w = (const float*)d_in[10];

    float* out  = (float*)d_out;
    float* hout = out + (size_t)BL_ * D_;

    float* p_xsc = nullptr;
    float* p_y   = nullptr;
    cudaGetSymbolAddress((void**)&p_xsc, g_xsc);
    cudaGetSymbolAddress((void**)&p_y,   g_y);

    const int SMEM_GEMM = 2 * STAGE_B;   // 61440 bytes
    cudaFuncSetAttribute(gemm_mma<0>, cudaFuncAttributeMaxDynamicSharedMemorySize, SMEM_GEMM);
    cudaFuncSetAttribute(gemm_mma<1>, cudaFuncAttributeMaxDynamicSharedMemorySize, SMEM_GEMM);

    // 1. A = -exp(A_log)
    prep_A_kernel<<<(ED_ * N_ + 255) / 256, 256>>>(A_log);

    // 2. in_proj GEMM (3xFP16, SMEM-resident split): split xs / z
    gemm_mma<1><<<dim3(NPROJ / 128, BL_ / 64), 128, SMEM_GEMM>>>(
        x, in_proj_w, nullptr, NPROJ, D_);

    // 3. depthwise conv + silu
    conv_silu_kernel<<<(BL_ * (ED_ / 4) + 255) / 256, 256>>>(conv_w, conv_b);

    // 4. x_proj GEMM (split-K SIMT) + reduce
    gemm_xproj_sk<<<dim3(1, BL_ / 64, SPLITK), 256>>>(p_xsc, x_proj_w, ED_);
    reduce_xdbl_kernel<<<(BL_ * 64 / 4 + 255) / 256, 256>>>();

    // 5. dt_proj + softplus -> delta
    delta_kernel<<<(BL_ / 8) * 8, 256>>>(dt_proj_w, dt_proj_b);

    // 6. fused SSM (writes h_new to output + y*silu(z) scratch)
    ssm_kernel<<<BL_ * 8, 256>>>(h, Dvec, hout);

    // 7. out_proj GEMM (3xFP16, SMEM-resident split)
    gemm_mma<0><<<dim3(D_ / 128, BL_ / 64), 128, SMEM_GEMM>>>(
        p_y, out_proj_w, out, D_, ED_);
}

// round 8
// speedup vs baseline: 1.5762x; 1.1041x over previous
#include <cuda_runtime.h>
#include <cuda_fp16.h>
#include <cstdint>

// Problem constants (fixed shapes)
#define BL_   2048           // B*L = 2*1024
#define L_    1024
#define D_    1024
#define ED_   2048
#define N_    16
#define R_    32
#define NPROJ 4096           // 2*ED
#define SPLITK 16

// ---------------- device scratch (static, no allocation) ----------------
__device__ float g_xs  [BL_ * ED_];
__device__ float g_z   [BL_ * ED_];
__device__ float g_xsc [BL_ * ED_];
__device__ float g_xdbl[BL_ * 64];
__device__ float g_xdbl_part[SPLITK][BL_ * 64];
__device__ float g_y   [BL_ * ED_];
__device__ float g_A   [ED_ * N_];

// ---------------- helpers ----------------
// split float4 (4 consecutive k) into packed half2 hi pair + lo pair
__device__ __forceinline__ void split4(float4 v, uint2& hi, uint2& lo) {
    __half2 h0 = __floats2half2_rn(v.x, v.y);
    __half2 h1 = __floats2half2_rn(v.z, v.w);
    float2 f0 = __half22float2(h0);
    float2 f1 = __half22float2(h1);
    __half2 l0 = __floats2half2_rn(v.x - f0.x, v.y - f0.y);
    __half2 l1 = __floats2half2_rn(v.z - f1.x, v.w - f1.y);
    hi.x = *reinterpret_cast<uint32_t*>(&h0);
    hi.y = *reinterpret_cast<uint32_t*>(&h1);
    lo.x = *reinterpret_cast<uint32_t*>(&l0);
    lo.y = *reinterpret_cast<uint32_t*>(&l1);
}
__device__ __forceinline__ void split4hi(float4 v, uint2& hi) {
    __half2 h0 = __floats2half2_rn(v.x, v.y);
    __half2 h1 = __floats2half2_rn(v.z, v.w);
    hi.x = *reinterpret_cast<uint32_t*>(&h0);
    hi.y = *reinterpret_cast<uint32_t*>(&h1);
}

#define MMA_F16(c, a0, a1, a2, a3, b0, b1) \
    asm volatile("mma.sync.aligned.m16n8k16.row.col.f32.f16.f16.f32 " \
        "{%0,%1,%2,%3}, {%4,%5,%6,%7}, {%8,%9}, {%0,%1,%2,%3};" \
        : "+f"((c)[0]), "+f"((c)[1]), "+f"((c)[2]), "+f"((c)[3]) \
        : "r"(a0), "r"(a1), "r"(a2), "r"(a3), "r"(b0), "r"(b1))

// ============================================================
// FP16 split mma.sync GEMM, hi/lo split ONCE at tile load.
// BTERMS=2: D += Ahi*Bhi + Ahi*Blo + Alo*Bhi (3 MMAs)
// BTERMS=1: D += Ahi*Bhi + Alo*Bhi           (2 MMAs, B hi-only)
// CTA 64x128, BK=32, 128 threads = 4 warps (2m x 2n), warp 32x64.
// SMEM fp16 tiles, PADH=40 halves/row (conflict-free frags),
// register-double-buffered LDG->cvt->STS producer.
// EPI 0: C[m*Nout+n];  EPI 1: split to g_xs / g_z.
// ============================================================
#define PADH 40                          // halves per row (80 B)
#define AHI_OFF 0
#define ALO_OFF 5120                     // 64*80
#define BHI_OFF 10240
#define BLO_OFF 20480                    // +128*80
#define STAGE_B 30720                    // bytes per stage

template<int EPI, int BTERMS>
__global__ void __launch_bounds__(128, 2)
gemm_mma(const float* __restrict__ A, const float* __restrict__ B,
         float* __restrict__ C, int Nout, int K)
{
    extern __shared__ char smem[];
    const int tid  = threadIdx.x;
    const int wid  = tid >> 5;           // 0..3
    const int lane = tid & 31;
    const int gq   = lane >> 2;          // 0..7
    const int tig  = lane & 3;           // 0..3
    const int m0   = blockIdx.y * 64;
    const int n0   = blockIdx.x * 128;
    const int wm   = (wid >> 1) * 32;    // warp m offset
    const int wn   = (wid & 1) * 64;     // warp n offset
    const int NC   = K >> 5;

    float acc[2][8][4];
#pragma unroll
    for (int i = 0; i < 2; i++)
#pragma unroll
        for (int j = 0; j < 8; j++)
#pragma unroll
            for (int q = 0; q < 4; q++) acc[i][j][q] = 0.f;

    // loader mapping: 16 rows x 8 col-quads
    const int lr  = tid >> 3;            // 0..15
    const int lc4 = (tid & 7) << 2;      // 0,4,...,28
    const float* ga = A + (size_t)(m0 + lr) * K + lc4;
    const float* gb = B + (size_t)(n0 + lr) * K + lc4;
    const uint32_t sO = (uint32_t)(lr * PADH + lc4) * 2;

    float4 pfA[4], pfB[8];

    auto ldg_chunk = [&](int c) {
        const float* pa = ga + c * 32;
        const float* pb = gb + c * 32;
#pragma unroll
        for (int i = 0; i < 4; i++) pfA[i] = *(const float4*)(pa + (size_t)(i * 16) * K);
#pragma unroll
        for (int i = 0; i < 8; i++) pfB[i] = *(const float4*)(pb + (size_t)(i * 16) * K);
    };
    auto sts_chunk = [&](int buf) {
        char* st = smem + buf * STAGE_B;
#pragma unroll
        for (int i = 0; i < 4; i++) {
            uint2 hi, lo; split4(pfA[i], hi, lo);
            uint32_t o = sO + (uint32_t)(i * 16 * PADH) * 2;
            *(uint2*)(st + AHI_OFF + o) = hi;
            *(uint2*)(st + ALO_OFF + o) = lo;
        }
#pragma unroll
        for (int i = 0; i < 8; i++) {
            uint32_t o = sO + (uint32_t)(i * 16 * PADH) * 2;
            if (BTERMS == 2) {
                uint2 hi, lo; split4(pfB[i], hi, lo);
                *(uint2*)(st + BHI_OFF + o) = hi;
                *(uint2*)(st + BLO_OFF + o) = lo;
            } else {
                uint2 hi; split4hi(pfB[i], hi);
                *(uint2*)(st + BHI_OFF + o) = hi;
            }
        }
    };

    // ---- prologue ----
    ldg_chunk(0);
    sts_chunk(0);
    if (NC > 1) ldg_chunk(1);
    __syncthreads();

    for (int c = 0; c < NC; c++) {
        const int buf = c & 1;
        if (c + 1 < NC) sts_chunk((c + 1) & 1);
        if (c + 2 < NC) ldg_chunk(c + 2);

        const char* Ahi = smem + buf * STAGE_B + AHI_OFF;
        const char* Alo = smem + buf * STAGE_B + ALO_OFF;
        const char* Bhi = smem + buf * STAGE_B + BHI_OFF;
        const char* Blo = smem + buf * STAGE_B + BLO_OFF;

#pragma unroll
        for (int ks = 0; ks < 2; ks++) {
            uint32_t bh[8][2], bl[8][2];
#pragma unroll
            for (int nt = 0; nt < 8; nt++) {
                uint32_t ro = (uint32_t)((wn + 8 * nt + gq) * PADH + ks * 16 + 2 * tig) * 2;
                bh[nt][0] = *(const uint32_t*)(Bhi + ro);
                bh[nt][1] = *(const uint32_t*)(Bhi + ro + 16);
                if (BTERMS == 2) {
                    bl[nt][0] = *(const uint32_t*)(Blo + ro);
                    bl[nt][1] = *(const uint32_t*)(Blo + ro + 16);
                }
            }
#pragma unroll
            for (int mt = 0; mt < 2; mt++) {
                uint32_t ro = (uint32_t)((wm + 16 * mt + gq) * PADH + ks * 16 + 2 * tig) * 2;
                uint32_t ah[4], al[4];
                ah[0] = *(const uint32_t*)(Ahi + ro);
                ah[1] = *(const uint32_t*)(Ahi + ro + 8 * PADH * 2);
                ah[2] = *(const uint32_t*)(Ahi + ro + 16);
                ah[3] = *(const uint32_t*)(Ahi + ro + 8 * PADH * 2 + 16);
                al[0] = *(const uint32_t*)(Alo + ro);
                al[1] = *(const uint32_t*)(Alo + ro + 8 * PADH * 2);
                al[2] = *(const uint32_t*)(Alo + ro + 16);
                al[3] = *(const uint32_t*)(Alo + ro + 8 * PADH * 2 + 16);
#pragma unroll
                for (int nt = 0; nt < 8; nt++) {
                    MMA_F16(acc[mt][nt], ah[0], ah[1], ah[2], ah[3], bh[nt][0], bh[nt][1]);
                    if (BTERMS == 2)
                        MMA_F16(acc[mt][nt], ah[0], ah[1], ah[2], ah[3], bl[nt][0], bl[nt][1]);
                    MMA_F16(acc[mt][nt], al[0], al[1], al[2], al[3], bh[nt][0], bh[nt][1]);
                }
            }
        }
        __syncthreads();
    }

    // ---- epilogue ----
    float* dst;
    int ld, ncol0;
    if (EPI == 1) {
        if (n0 < ED_) { dst = g_xs; ncol0 = n0; }
        else          { dst = g_z;  ncol0 = n0 - ED_; }
        ld = ED_;
    } else {
        dst = C; ncol0 = n0; ld = Nout;
    }
#pragma unroll
    for (int mt = 0; mt < 2; mt++) {
        const int m = m0 + wm + 16 * mt + gq;
#pragma unroll
        for (int nt = 0; nt < 8; nt++) {
            const int n = ncol0 + wn + 8 * nt + 2 * tig;
            float2 v0 = make_float2(acc[mt][nt][0], acc[mt][nt][1]);
            float2 v1 = make_float2(acc[mt][nt][2], acc[mt][nt][3]);
            *(float2*)(dst + (size_t)m * ld + n)       = v0;
            *(float2*)(dst + (size_t)(m + 8) * ld + n) = v1;
        }
    }
}

// ---------------- tiny precompute: A = -exp(A_log) ----------------
__global__ void prep_A_kernel(const float* __restrict__ A_log) {
    int i = blockIdx.x * blockDim.x + threadIdx.x;
    if (i < ED_ * N_) g_A[i] = -expf(A_log[i]);
}

// ---------------- fused conv+silu + split-K x_proj GEMM ----------------
// A tile computed on the fly: xsc[m][e] = silu(conv(g_xs)); also written to g_xsc.
// grid (1, M/64, SPLITK); block 256. K-slice = 2048/16 = 128 (e-range).
__global__ void __launch_bounds__(256)
gemm_xproj_fused(const float* __restrict__ B,     // x_proj_w (64,2048)
                 const float* __restrict__ cw,    // conv_w (2048*3)
                 const float* __restrict__ cb,    // conv_b
                 int K)
{
    constexpr int BM = 64, BN = 64, BK = 16, TM = 4, TN = 4;
    __shared__ float As[BK * BM];
    __shared__ float Bs[BK * BN];

    const int t  = threadIdx.x;
    const int m0 = blockIdx.y * BM;
    const int z  = blockIdx.z;
    const int KS = K / SPLITK;
    const int kbeg = z * KS;
    const int tr = t / (BN / TN);
    const int tc = t % (BN / TN);

    float acc[TM][TN];
#pragma unroll
    for (int i = 0; i < TM; i++)
#pragma unroll
        for (int j = 0; j < TN; j++) acc[i][j] = 0.f;

    const int row = t >> 2;          // 0..63
    const int cc  = t & 3;           // 0..3
    const int m   = m0 + row;
    const int l   = m & (L_ - 1);

    for (int k0 = kbeg; k0 < kbeg + KS; k0 += BK) {
        {
            const int e = k0 + cc * 4;
            // conv inputs
            float4 cur  = *(const float4*)(g_xs + (size_t)m * ED_ + e);
            float4 prev = (l > 0)      ? *(const float4*)(g_xs + (size_t)(m - 1) * ED_ + e)
                                       : make_float4(0.f, 0.f, 0.f, 0.f);
            float4 nxt  = (l < L_ - 1) ? *(const float4*)(g_xs + (size_t)(m + 1) * ED_ + e)
                                       : make_float4(0.f, 0.f, 0.f, 0.f);
            float4 w0 = *(const float4*)(cw + (size_t)e * 3);
            float4 w1 = *(const float4*)(cw + (size_t)e * 3 + 4);
            float4 w2 = *(const float4*)(cw + (size_t)e * 3 + 8);
            float4 bb = *(const float4*)(cb + e);

            float r0 = fmaf(prev.x, w0.x, fmaf(cur.x, w0.y, fmaf(nxt.x, w0.z, bb.x)));
            float r1 = fmaf(prev.y, w0.w, fmaf(cur.y, w1.x, fmaf(nxt.y, w1.y, bb.y)));
            float r2 = fmaf(prev.z, w1.z, fmaf(cur.z, w1.w, fmaf(nxt.z, w2.x, bb.z)));
            float r3 = fmaf(prev.w, w2.y, fmaf(cur.w, w2.z, fmaf(nxt.w, w2.w, bb.w)));

            float4 o;
            o.x = r0 * (1.f / (1.f + __expf(-r0)));
            o.y = r1 * (1.f / (1.f + __expf(-r1)));
            o.z = r2 * (1.f / (1.f + __expf(-r2)));
            o.w = r3 * (1.f / (1.f + __expf(-r3)));
            *(float4*)(g_xsc + (size_t)m * ED_ + e) = o;   // each (m,e) written once

            As[(cc * 4 + 0) * BM + row] = o.x;
            As[(cc * 4 + 1) * BM + row] = o.y;
            As[(cc * 4 + 2) * BM + row] = o.z;
            As[(cc * 4 + 3) * BM + row] = o.w;

            float4 w = *(const float4*)(B + (size_t)row * K + k0 + cc * 4);
            Bs[(cc * 4 + 0) * BN + row] = w.x;
            Bs[(cc * 4 + 1) * BN + row] = w.y;
            Bs[(cc * 4 + 2) * BN + row] = w.z;
            Bs[(cc * 4 + 3) * BN + row] = w.w;
        }
        __syncthreads();
#pragma unroll
        for (int kk = 0; kk < BK; kk++) {
            float af[TM], bf[TN];
#pragma unroll
            for (int i = 0; i < TM; i++) af[i] = As[kk * BM + tr * TM + i];
#pragma unroll
            for (int j = 0; j < TN; j++) bf[j] = Bs[kk * BN + tc * TN + j];
#pragma unroll
            for (int i = 0; i < TM; i++)
#pragma unroll
                for (int j = 0; j < TN; j++)
                    acc[i][j] = fmaf(af[i], bf[j], acc[i][j]);
        }
        __syncthreads();
    }
#pragma unroll
    for (int i = 0; i < TM; i++) {
        int mm = m0 + tr * TM + i;
#pragma unroll
        for (int j = 0; j < TN; j++) {
            int n = tc * TN + j;
            g_xdbl_part[z][(size_t)mm * 64 + n] = acc[i][j];
        }
    }
}

__global__ void reduce_xdbl_kernel() {
    int i = blockIdx.x * blockDim.x + threadIdx.x;
    if (i >= BL_ * 64 / 4) return;
    float4 s = make_float4(0.f, 0.f, 0.f, 0.f);
#pragma unroll
    for (int z = 0; z < SPLITK; z++) {
        float4 v = *((const float4*)g_xdbl_part[z] + i);
        s.x += v.x; s.y += v.y; s.z += v.z; s.w += v.w;
    }
    *((float4*)g_xdbl + i) = s;
}

// ---------------- fused delta + SSM step ----------------
// Block: 256 threads, covers 8 tokens (m) x 256 channels (e).
// Per thread: delta = softplus(xdbl[m][0:32] . W[e] + b[e]) computed inline,
// W/A/D loaded once and reused across the 8 tokens.
__global__ void __launch_bounds__(256)
ssm_fused(const float* __restrict__ h,
          const float* __restrict__ W,      // dt_proj_w (2048,32)
          const float* __restrict__ bias,   // dt_proj_b
          const float* __restrict__ Dvec,
          float* __restrict__ hout)
{
    const int tid = threadIdx.x;
    const int s   = blockIdx.x & 7;
    const int mg  = blockIdx.x >> 3;
    const int e   = (s << 8) + tid;

    __shared__ float sx[8][64];
    {
        int idx = tid * 2;
        float2 v = *(const float2*)(g_xdbl + (size_t)(mg * 8 + (idx >> 6)) * 64 + (idx & 63));
        sx[idx >> 6][idx & 63]       = v.x;
        sx[idx >> 6][(idx & 63) + 1] = v.y;
    }
    __syncthreads();

    float wr[32];
#pragma unroll
    for (int q = 0; q < 8; q++) {
        float4 v = *(const float4*)(W + (size_t)e * 32 + q * 4);
        wr[q * 4 + 0] = v.x; wr[q * 4 + 1] = v.y; wr[q * 4 + 2] = v.z; wr[q * 4 + 3] = v.w;
    }
    const float bv   = bias[e];
    const float dval = Dvec[e];
    float4 a4[4];
#pragma unroll
    for (int q = 0; q < 4; q++) a4[q] = ((const float4*)(g_A + (size_t)e * N_))[q];

#pragma unroll
    for (int mm = 0; mm < 8; mm++) {
        const int m = mg * 8 + mm;
        float acc = bv;
#pragma unroll
        for (int r = 0; r < 32; r++) acc = fmaf(sx[mm][r], wr[r], acc);
        const float delta = (acc > 20.f) ? acc : log1pf(__expf(acc));

        const size_t me = (size_t)m * ED_ + e;
        const float xs = g_xsc[me];
        const float z  = g_z[me];
        const float dx = delta * xs;

        const float4* h4 = (const float4*)(h + me * N_);
        float4*       o4 = (float4*)(hout + me * N_);

        float y = 0.f;
#pragma unroll
        for (int q = 0; q < 4; q++) {
            float4 hv = h4[q];
            float4 av = a4[q];
            float4 o;
            o.x = fmaf(__expf(delta * av.x), hv.x, dx * sx[mm][32 + q * 4 + 0]);
            o.y = fmaf(__expf(delta * av.y), hv.y, dx * sx[mm][32 + q * 4 + 1]);
            o.z = fmaf(__expf(delta * av.z), hv.z, dx * sx[mm][32 + q * 4 + 2]);
            o.w = fmaf(__expf(delta * av.w), hv.w, dx * sx[mm][32 + q * 4 + 3]);
            o4[q] = o;
            y = fmaf(o.x, sx[mm][48 + q * 4 + 0], y);
            y = fmaf(o.y, sx[mm][48 + q * 4 + 1], y);
            y = fmaf(o.z, sx[mm][48 + q * 4 + 2], y);
            y = fmaf(o.w, sx[mm][48 + q * 4 + 3], y);
        }
        y = fmaf(dval, xs, y);
        const float sz = z * (1.f / (1.f + __expf(-z)));
        g_y[me] = y * sz;
    }
}

// ---------------- launch ----------------
extern "C" void kernel_launch(void* const* d_in, const int* in_sizes, int n_in,
                              void* d_out, int out_size)
{
    const float* x          = (const float*)d_in[0];
    const float* h          = (const float*)d_in[1];
    const float* in_proj_w  = (const float*)d_in[2];
    const float* conv_w     = (const float*)d_in[3];
    const float* conv_b     = (const float*)d_in[4];
    const float* x_proj_w   = (const float*)d_in[5];
    const float* dt_proj_w  = (const float*)d_in[6];
    const float* dt_proj_b  = (const float*)d_in[7];
    const float* A_log      = (const float*)d_in[8];
    const float* Dvec       = (const float*)d_in[9];
    const float* out_proj_w = (const float*)d_in[10];

    float* out  = (float*)d_out;
    float* hout = out + (size_t)BL_ * D_;

    float* p_y = nullptr;
    cudaGetSymbolAddress((void**)&p_y, g_y);

    const int SMEM_GEMM = 2 * STAGE_B;   // 61440 bytes
    cudaFuncSetAttribute(gemm_mma<1, 2>, cudaFuncAttributeMaxDynamicSharedMemorySize, SMEM_GEMM);
    cudaFuncSetAttribute(gemm_mma<0, 1>, cudaFuncAttributeMaxDynamicSharedMemorySize, SMEM_GEMM);

    // 1. A = -exp(A_log)
    prep_A_kernel<<<(ED_ * N_ + 255) / 256, 256>>>(A_log);

    // 2. in_proj GEMM (3-term fp16 split): split xs / z
    gemm_mma<1, 2><<<dim3(NPROJ / 128, BL_ / 64), 128, SMEM_GEMM>>>(
        x, in_proj_w, nullptr, NPROJ, D_);

    // 3. x_proj GEMM with fused conv+silu (writes g_xsc), split-K + reduce
    gemm_xproj_fused<<<dim3(1, BL_ / 64, SPLITK), 256>>>(x_proj_w, conv_w, conv_b, ED_);
    reduce_xdbl_kernel<<<(BL_ * 64 / 4 + 255) / 256, 256>>>();

    // 4. fused delta + SSM (writes h_new to output + y*silu(z) scratch)
    ssm_fused<<<(BL_ / 8) * 8, 256>>>(h, dt_proj_w, dt_proj_b, Dvec, hout);

    // 5. out_proj GEMM (2-term fp16 split)
    gemm_mma<0, 1><<<dim3(D_ / 128, BL_ / 64), 128, SMEM_GEMM>>>(
        p_y, out_proj_w, out, D_, ED_);
}

// round 9
// speedup vs baseline: 1.7776x; 1.1278x over previous
#include <cuda_runtime.h>
#include <cuda_fp16.h>
#include <cstdint>

// Problem constants (fixed shapes)
#define BL_   2048           // B*L = 2*1024
#define L_    1024
#define D_    1024
#define ED_   2048
#define N_    16
#define R_    32
#define NPROJ 4096           // 2*ED
#define SPLITK 16

// ---------------- device scratch (static, no allocation) ----------------
__device__ float g_xs  [BL_ * ED_];
__device__ float g_z   [BL_ * ED_];
__device__ float g_xsc [BL_ * ED_];
__device__ float g_xdbl[BL_ * 64];
__device__ float g_xdbl_part[SPLITK][BL_ * 64];
__device__ float g_y   [BL_ * ED_];
__device__ float g_A   [ED_ * N_];

// ---------------- helpers ----------------
// split float4 (4 consecutive k) into packed half2 hi pair + lo pair
__device__ __forceinline__ void split4(float4 v, uint2& hi, uint2& lo) {
    __half2 h0 = __floats2half2_rn(v.x, v.y);
    __half2 h1 = __floats2half2_rn(v.z, v.w);
    float2 f0 = __half22float2(h0);
    float2 f1 = __half22float2(h1);
    __half2 l0 = __floats2half2_rn(v.x - f0.x, v.y - f0.y);
    __half2 l1 = __floats2half2_rn(v.z - f1.x, v.w - f1.y);
    hi.x = *reinterpret_cast<uint32_t*>(&h0);
    hi.y = *reinterpret_cast<uint32_t*>(&h1);
    lo.x = *reinterpret_cast<uint32_t*>(&l0);
    lo.y = *reinterpret_cast<uint32_t*>(&l1);
}
__device__ __forceinline__ void split4hi(float4 v, uint2& hi) {
    __half2 h0 = __floats2half2_rn(v.x, v.y);
    __half2 h1 = __floats2half2_rn(v.z, v.w);
    hi.x = *reinterpret_cast<uint32_t*>(&h0);
    hi.y = *reinterpret_cast<uint32_t*>(&h1);
}

#define MMA_F16(c, a0, a1, a2, a3, b0, b1) \
    asm volatile("mma.sync.aligned.m16n8k16.row.col.f32.f16.f16.f32 " \
        "{%0,%1,%2,%3}, {%4,%5,%6,%7}, {%8,%9}, {%0,%1,%2,%3};" \
        : "+f"((c)[0]), "+f"((c)[1]), "+f"((c)[2]), "+f"((c)[3]) \
        : "r"(a0), "r"(a1), "r"(a2), "r"(a3), "r"(b0), "r"(b1))

// ============================================================
// FP16 split mma.sync GEMM, hi/lo split ONCE at tile load.
// BTERMS=2: D += Ahi*Bhi + Ahi*Blo + Alo*Bhi (3 MMAs)
// BTERMS=1: D += Ahi*Bhi + Alo*Bhi           (2 MMAs, B hi-only)
// CTA 64x128, BK=32, 128 threads = 4 warps (2m x 2n), warp 32x64.
// SMEM fp16 tiles, PADH=40 halves/row (conflict-free frags),
// register-double-buffered LDG->cvt->STS producer.
// EPI 0: C[m*Nout+n];  EPI 1: split to g_xs / g_z.
// ============================================================
#define PADH 40                          // halves per row (80 B)
#define AHI_OFF 0
#define ALO_OFF 5120                     // 64*80
#define BHI_OFF 10240
#define BLO_OFF 20480                    // +128*80
#define STAGE_B 30720                    // bytes per stage

template<int EPI, int BTERMS>
__global__ void __launch_bounds__(128, 2)
gemm_mma(const float* __restrict__ A, const float* __restrict__ B,
         float* __restrict__ C, int Nout, int K)
{
    extern __shared__ char smem[];
    const int tid  = threadIdx.x;
    const int wid  = tid >> 5;           // 0..3
    const int lane = tid & 31;
    const int gq   = lane >> 2;          // 0..7
    const int tig  = lane & 3;           // 0..3
    const int m0   = blockIdx.y * 64;
    const int n0   = blockIdx.x * 128;
    const int wm   = (wid >> 1) * 32;    // warp m offset
    const int wn   = (wid & 1) * 64;     // warp n offset
    const int NC   = K >> 5;

    float acc[2][8][4];
#pragma unroll
    for (int i = 0; i < 2; i++)
#pragma unroll
        for (int j = 0; j < 8; j++)
#pragma unroll
            for (int q = 0; q < 4; q++) acc[i][j][q] = 0.f;

    // loader mapping: 16 rows x 8 col-quads
    const int lr  = tid >> 3;            // 0..15
    const int lc4 = (tid & 7) << 2;      // 0,4,...,28
    const float* ga = A + (size_t)(m0 + lr) * K + lc4;
    const float* gb = B + (size_t)(n0 + lr) * K + lc4;
    const uint32_t sO = (uint32_t)(lr * PADH + lc4) * 2;

    float4 pfA[4], pfB[8];

    auto ldg_chunk = [&](int c) {
        const float* pa = ga + c * 32;
        const float* pb = gb + c * 32;
#pragma unroll
        for (int i = 0; i < 4; i++) pfA[i] = *(const float4*)(pa + (size_t)(i * 16) * K);
#pragma unroll
        for (int i = 0; i < 8; i++) pfB[i] = *(const float4*)(pb + (size_t)(i * 16) * K);
    };
    auto sts_chunk = [&](int buf) {
        char* st = smem + buf * STAGE_B;
#pragma unroll
        for (int i = 0; i < 4; i++) {
            uint2 hi, lo; split4(pfA[i], hi, lo);
            uint32_t o = sO + (uint32_t)(i * 16 * PADH) * 2;
            *(uint2*)(st + AHI_OFF + o) = hi;
            *(uint2*)(st + ALO_OFF + o) = lo;
        }
#pragma unroll
        for (int i = 0; i < 8; i++) {
            uint32_t o = sO + (uint32_t)(i * 16 * PADH) * 2;
            if (BTERMS == 2) {
                uint2 hi, lo; split4(pfB[i], hi, lo);
                *(uint2*)(st + BHI_OFF + o) = hi;
                *(uint2*)(st + BLO_OFF + o) = lo;
            } else {
                uint2 hi; split4hi(pfB[i], hi);
                *(uint2*)(st + BHI_OFF + o) = hi;
            }
        }
    };

    // ---- prologue ----
    ldg_chunk(0);
    sts_chunk(0);
    if (NC > 1) ldg_chunk(1);
    __syncthreads();

    for (int c = 0; c < NC; c++) {
        const int buf = c & 1;
        if (c + 1 < NC) sts_chunk((c + 1) & 1);
        if (c + 2 < NC) ldg_chunk(c + 2);

        const char* Ahi = smem + buf * STAGE_B + AHI_OFF;
        const char* Alo = smem + buf * STAGE_B + ALO_OFF;
        const char* Bhi = smem + buf * STAGE_B + BHI_OFF;
        const char* Blo = smem + buf * STAGE_B + BLO_OFF;

#pragma unroll
        for (int ks = 0; ks < 2; ks++) {
            uint32_t bh[8][2], bl[8][2];
#pragma unroll
            for (int nt = 0; nt < 8; nt++) {
                uint32_t ro = (uint32_t)((wn + 8 * nt + gq) * PADH + ks * 16 + 2 * tig) * 2;
                bh[nt][0] = *(const uint32_t*)(Bhi + ro);
                bh[nt][1] = *(const uint32_t*)(Bhi + ro + 16);
                if (BTERMS == 2) {
                    bl[nt][0] = *(const uint32_t*)(Blo + ro);
                    bl[nt][1] = *(const uint32_t*)(Blo + ro + 16);
                }
            }
#pragma unroll
            for (int mt = 0; mt < 2; mt++) {
                uint32_t ro = (uint32_t)((wm + 16 * mt + gq) * PADH + ks * 16 + 2 * tig) * 2;
                uint32_t ah[4], al[4];
                ah[0] = *(const uint32_t*)(Ahi + ro);
                ah[1] = *(const uint32_t*)(Ahi + ro + 8 * PADH * 2);
                ah[2] = *(const uint32_t*)(Ahi + ro + 16);
                ah[3] = *(const uint32_t*)(Ahi + ro + 8 * PADH * 2 + 16);
                al[0] = *(const uint32_t*)(Alo + ro);
                al[1] = *(const uint32_t*)(Alo + ro + 8 * PADH * 2);
                al[2] = *(const uint32_t*)(Alo + ro + 16);
                al[3] = *(const uint32_t*)(Alo + ro + 8 * PADH * 2 + 16);
#pragma unroll
                for (int nt = 0; nt < 8; nt++) {
                    MMA_F16(acc[mt][nt], ah[0], ah[1], ah[2], ah[3], bh[nt][0], bh[nt][1]);
                    if (BTERMS == 2)
                        MMA_F16(acc[mt][nt], ah[0], ah[1], ah[2], ah[3], bl[nt][0], bl[nt][1]);
                    MMA_F16(acc[mt][nt], al[0], al[1], al[2], al[3], bh[nt][0], bh[nt][1]);
                }
            }
        }
        __syncthreads();
    }

    // ---- epilogue ----
    float* dst;
    int ld, ncol0;
    if (EPI == 1) {
        if (n0 < ED_) { dst = g_xs; ncol0 = n0; }
        else          { dst = g_z;  ncol0 = n0 - ED_; }
        ld = ED_;
    } else {
        dst = C; ncol0 = n0; ld = Nout;
    }
#pragma unroll
    for (int mt = 0; mt < 2; mt++) {
        const int m = m0 + wm + 16 * mt + gq;
#pragma unroll
        for (int nt = 0; nt < 8; nt++) {
            const int n = ncol0 + wn + 8 * nt + 2 * tig;
            float2 v0 = make_float2(acc[mt][nt][0], acc[mt][nt][1]);
            float2 v1 = make_float2(acc[mt][nt][2], acc[mt][nt][3]);
            *(float2*)(dst + (size_t)m * ld + n)       = v0;
            *(float2*)(dst + (size_t)(m + 8) * ld + n) = v1;
        }
    }
}

// ---------------- tiny precompute: A = -exp(A_log) ----------------
__global__ void prep_A_kernel(const float* __restrict__ A_log) {
    int i = blockIdx.x * blockDim.x + threadIdx.x;
    if (i < ED_ * N_) g_A[i] = -expf(A_log[i]);
}

// ---------------- fused conv+silu + split-K x_proj GEMM ----------------
// A tile computed on the fly: xsc[m][e] = silu(conv(g_xs)); also written to g_xsc.
// grid (1, M/64, SPLITK); block 256. K-slice = 2048/16 = 128 (e-range).
__global__ void __launch_bounds__(256)
gemm_xproj_fused(const float* __restrict__ B,     // x_proj_w (64,2048)
                 const float* __restrict__ cw,    // conv_w (2048*3)
                 const float* __restrict__ cb,    // conv_b
                 int K)
{
    constexpr int BM = 64, BN = 64, BK = 16, TM = 4, TN = 4;
    __shared__ float As[BK * BM];
    __shared__ float Bs[BK * BN];

    const int t  = threadIdx.x;
    const int m0 = blockIdx.y * BM;
    const int z  = blockIdx.z;
    const int KS = K / SPLITK;
    const int kbeg = z * KS;
    const int tr = t / (BN / TN);
    const int tc = t % (BN / TN);

    float acc[TM][TN];
#pragma unroll
    for (int i = 0; i < TM; i++)
#pragma unroll
        for (int j = 0; j < TN; j++) acc[i][j] = 0.f;

    const int row = t >> 2;          // 0..63
    const int cc  = t & 3;           // 0..3
    const int m   = m0 + row;
    const int l   = m & (L_ - 1);

    for (int k0 = kbeg; k0 < kbeg + KS; k0 += BK) {
        {
            const int e = k0 + cc * 4;
            // conv inputs
            float4 cur  = *(const float4*)(g_xs + (size_t)m * ED_ + e);
            float4 prev = (l > 0)      ? *(const float4*)(g_xs + (size_t)(m - 1) * ED_ + e)
                                       : make_float4(0.f, 0.f, 0.f, 0.f);
            float4 nxt  = (l < L_ - 1) ? *(const float4*)(g_xs + (size_t)(m + 1) * ED_ + e)
                                       : make_float4(0.f, 0.f, 0.f, 0.f);
            float4 w0 = *(const float4*)(cw + (size_t)e * 3);
            float4 w1 = *(const float4*)(cw + (size_t)e * 3 + 4);
            float4 w2 = *(const float4*)(cw + (size_t)e * 3 + 8);
            float4 bb = *(const float4*)(cb + e);

            float r0 = fmaf(prev.x, w0.x, fmaf(cur.x, w0.y, fmaf(nxt.x, w0.z, bb.x)));
            float r1 = fmaf(prev.y, w0.w, fmaf(cur.y, w1.x, fmaf(nxt.y, w1.y, bb.y)));
            float r2 = fmaf(prev.z, w1.z, fmaf(cur.z, w1.w, fmaf(nxt.z, w2.x, bb.z)));
            float r3 = fmaf(prev.w, w2.y, fmaf(cur.w, w2.z, fmaf(nxt.w, w2.w, bb.w)));

            float4 o;
            o.x = r0 * (1.f / (1.f + __expf(-r0)));
            o.y = r1 * (1.f / (1.f + __expf(-r1)));
            o.z = r2 * (1.f / (1.f + __expf(-r2)));
            o.w = r3 * (1.f / (1.f + __expf(-r3)));
            *(float4*)(g_xsc + (size_t)m * ED_ + e) = o;   // each (m,e) written once

            As[(cc * 4 + 0) * BM + row] = o.x;
            As[(cc * 4 + 1) * BM + row] = o.y;
            As[(cc * 4 + 2) * BM + row] = o.z;
            As[(cc * 4 + 3) * BM + row] = o.w;

            float4 w = *(const float4*)(B + (size_t)row * K + k0 + cc * 4);
            Bs[(cc * 4 + 0) * BN + row] = w.x;
            Bs[(cc * 4 + 1) * BN + row] = w.y;
            Bs[(cc * 4 + 2) * BN + row] = w.z;
            Bs[(cc * 4 + 3) * BN + row] = w.w;
        }
        __syncthreads();
#pragma unroll
        for (int kk = 0; kk < BK; kk++) {
            float af[TM], bf[TN];
#pragma unroll
            for (int i = 0; i < TM; i++) af[i] = As[kk * BM + tr * TM + i];
#pragma unroll
            for (int j = 0; j < TN; j++) bf[j] = Bs[kk * BN + tc * TN + j];
#pragma unroll
            for (int i = 0; i < TM; i++)
#pragma unroll
                for (int j = 0; j < TN; j++)
                    acc[i][j] = fmaf(af[i], bf[j], acc[i][j]);
        }
        __syncthreads();
    }
#pragma unroll
    for (int i = 0; i < TM; i++) {
        int mm = m0 + tr * TM + i;
#pragma unroll
        for (int j = 0; j < TN; j++) {
            int n = tc * TN + j;
            g_xdbl_part[z][(size_t)mm * 64 + n] = acc[i][j];
        }
    }
}

__global__ void reduce_xdbl_kernel() {
    int i = blockIdx.x * blockDim.x + threadIdx.x;
    if (i >= BL_ * 64 / 4) return;
    float4 s = make_float4(0.f, 0.f, 0.f, 0.f);
#pragma unroll
    for (int z = 0; z < SPLITK; z++) {
        float4 v = *((const float4*)g_xdbl_part[z] + i);
        s.x += v.x; s.y += v.y; s.z += v.z; s.w += v.w;
    }
    *((float4*)g_xdbl + i) = s;
}

// ---------------- fused delta + SSM step ----------------
// Block: 256 threads, covers 8 tokens (m) x 256 channels (e).
// Per thread: delta = softplus(xdbl[m][0:32] . W[e] + b[e]) computed inline,
// W/A/D loaded once and reused across the 8 tokens.
__global__ void __launch_bounds__(256)
ssm_fused(const float* __restrict__ h,
          const float* __restrict__ W,      // dt_proj_w (2048,32)
          const float* __restrict__ bias,   // dt_proj_b
          const float* __restrict__ Dvec,
          float* __restrict__ hout)
{
    const int tid = threadIdx.x;
    const int s   = blockIdx.x & 7;
    const int mg  = blockIdx.x >> 3;
    const int e   = (s << 8) + tid;

    __shared__ float sx[8][64];
    {
        int idx = tid * 2;
        float2 v = *(const float2*)(g_xdbl + (size_t)(mg * 8 + (idx >> 6)) * 64 + (idx & 63));
        sx[idx >> 6][idx & 63]       = v.x;
        sx[idx >> 6][(idx & 63) + 1] = v.y;
    }
    __syncthreads();

    float wr[32];
#pragma unroll
    for (int q = 0; q < 8; q++) {
        float4 v = *(const float4*)(W + (size_t)e * 32 + q * 4);
        wr[q * 4 + 0] = v.x; wr[q * 4 + 1] = v.y; wr[q * 4 + 2] = v.z; wr[q * 4 + 3] = v.w;
    }
    const float bv   = bias[e];
    const float dval = Dvec[e];
    float4 a4[4];
#pragma unroll
    for (int q = 0; q < 4; q++) a4[q] = ((const float4*)(g_A + (size_t)e * N_))[q];

#pragma unroll
    for (int mm = 0; mm < 8; mm++) {
        const int m = mg * 8 + mm;
        float acc = bv;
#pragma unroll
        for (int r = 0; r < 32; r++) acc = fmaf(sx[mm][r], wr[r], acc);
        const float delta = (acc > 20.f) ? acc : log1pf(__expf(acc));

        const size_t me = (size_t)m * ED_ + e;
        const float xs = g_xsc[me];
        const float z  = g_z[me];
        const float dx = delta * xs;

        const float4* h4 = (const float4*)(h + me * N_);
        float4*       o4 = (float4*)(hout + me * N_);

        float y = 0.f;
#pragma unroll
        for (int q = 0; q < 4; q++) {
            float4 hv = h4[q];
            float4 av = a4[q];
            float4 o;
            o.x = fmaf(__expf(delta * av.x), hv.x, dx * sx[mm][32 + q * 4 + 0]);
            o.y = fmaf(__expf(delta * av.y), hv.y, dx * sx[mm][32 + q * 4 + 1]);
            o.z = fmaf(__expf(delta * av.z), hv.z, dx * sx[mm][32 + q * 4 + 2]);
            o.w = fmaf(__expf(delta * av.w), hv.w, dx * sx[mm][32 + q * 4 + 3]);
            o4[q] = o;
            y = fmaf(o.x, sx[mm][48 + q * 4 + 0], y);
            y = fmaf(o.y, sx[mm][48 + q * 4 + 1], y);
            y = fmaf(o.z, sx[mm][48 + q * 4 + 2], y);
            y = fmaf(o.w, sx[mm][48 + q * 4 + 3], y);
        }
        y = fmaf(dval, xs, y);
        const float sz = z * (1.f / (1.f + __expf(-z)));
        g_y[me] = y * sz;
    }
}

// ---------------- launch ----------------
extern "C" void kernel_launch(void* const* d_in, const int* in_sizes, int n_in,
                              void* d_out, int out_size)
{
    const float* x          = (const float*)d_in[0];
    const float* h          = (const float*)d_in[1];
    const float* in_proj_w  = (const float*)d_in[2];
    const float* conv_w     = (const float*)d_in[3];
    const float* conv_b     = (const float*)d_in[4];
    const float* x_proj_w   = (const float*)d_in[5];
    const float* dt_proj_w  = (const float*)d_in[6];
    const float* dt_proj_b  = (const float*)d_in[7];
    const float* A_log      = (const float*)d_in[8];
    const float* Dvec       = (const float*)d_in[9];
    const float* out_proj_w = (const float*)d_in[10];

    float* out  = (float*)d_out;
    float* hout = out + (size_t)BL_ * D_;

    float* p_y = nullptr;
    cudaGetSymbolAddress((void**)&p_y, g_y);

    const int SMEM_GEMM = 2 * STAGE_B;   // 61440 bytes
    cudaFuncSetAttribute(gemm_mma<1, 1>, cudaFuncAttributeMaxDynamicSharedMemorySize, SMEM_GEMM);
    cudaFuncSetAttribute(gemm_mma<0, 1>, cudaFuncAttributeMaxDynamicSharedMemorySize, SMEM_GEMM);

    // 1. A = -exp(A_log)
    prep_A_kernel<<<(ED_ * N_ + 255) / 256, 256>>>(A_log);

    // 2. in_proj GEMM (2-term fp16 split): split xs / z
    gemm_mma<1, 1><<<dim3(NPROJ / 128, BL_ / 64), 128, SMEM_GEMM>>>(
        x, in_proj_w, nullptr, NPROJ, D_);

    // 3. x_proj GEMM with fused conv+silu (writes g_xsc), split-K + reduce
    gemm_xproj_fused<<<dim3(1, BL_ / 64, SPLITK), 256>>>(x_proj_w, conv_w, conv_b, ED_);
    reduce_xdbl_kernel<<<(BL_ * 64 / 4 + 255) / 256, 256>>>();

    // 4. fused delta + SSM (writes h_new to output + y*silu(z) scratch)
    ssm_fused<<<(BL_ / 8) * 8, 256>>>(h, dt_proj_w, dt_proj_b, Dvec, hout);

    // 5. out_proj GEMM (2-term fp16 split)
    gemm_mma<0, 1><<<dim3(D_ / 128, BL_ / 64), 128, SMEM_GEMM>>>(
        p_y, out_proj_w, out, D_, ED_);
}